// round 13
// baseline (speedup 1.0000x reference)
#include <cuda_runtime.h>
#include <cuda_fp16.h>
#include <cstdint>

// Problem constants (shapes fixed by the reference)
constexpr int NF = 512;   // input features
constexpr int NH = 256;   // hidden
constexpr int NC = 64;    // classes
constexpr int NNODE = 100000;

// Fixed-stride edge buckets: row r's edges at g_edges[r*SLOT .. r*SLOT+cnt).
// Degrees ~ Poisson(32); max over 100k rows ~58; SLOT=96 is an 11-sigma bound.
constexpr int SLOT = 96;

// Scratch (allocation-free rule: __device__ globals)
__device__ __half g_xw1[(size_t)NNODE * NH];  // x @ W1 (fp16)
__device__ __half g_h[(size_t)NNODE * NH];    // spmm1 out / h (fp16)
__device__ __half g_hw2[(size_t)NNODE * NC];  // h @ W2 (fp16)
__device__ int    g_cursor[NNODE];            // per-row edge count
__device__ int2   g_edges[(size_t)NNODE * SLOT];  // (col, val-bits), bucketed by row

// ---------------------------------------------------------------------------
__device__ __forceinline__ void mma_f16(float c[4], const uint32_t a[4], const uint32_t b[2]) {
    asm volatile(
        "mma.sync.aligned.m16n8k16.row.col.f32.f16.f16.f32 "
        "{%0,%1,%2,%3}, {%4,%5,%6,%7}, {%8,%9}, {%0,%1,%2,%3};"
        : "+f"(c[0]), "+f"(c[1]), "+f"(c[2]), "+f"(c[3])
        : "r"(a[0]), "r"(a[1]), "r"(a[2]), "r"(a[3]), "r"(b[0]), "r"(b[1]));
}

__device__ __forceinline__ void stcs_u4(uint4* p, uint4 v) {
    asm volatile("st.global.cs.v4.u32 [%0], {%1,%2,%3,%4};"
                 :: "l"(p), "r"(v.x), "r"(v.y), "r"(v.z), "r"(v.w) : "memory");
}

// ---------------------------------------------------------------------------
// Bucketed edge build: zero counters, then one scatter pass (atomicAdd gives
// both the count and the slot index — no histogram, no prefix scan).
__global__ void k_zero_cnt() {
    int i = blockIdx.x * blockDim.x + threadIdx.x;
    if (i < NNODE) g_cursor[i] = 0;
}

__global__ void k_scatter_direct(const int* __restrict__ rows, const int* __restrict__ cols,
                                 const float* __restrict__ vals, int E) {
    int e = blockIdx.x * blockDim.x + threadIdx.x;
    if (e >= E) return;
    int r = rows[e];
    int slot = atomicAdd(&g_cursor[r], 1);
    g_edges[(size_t)r * SLOT + slot] = make_int2(cols[e], __float_as_int(vals[e]));
}

// ---------------------------------------------------------------------------
// FP16 GEMM (m16n8k16, fp32 accum), BM=128 x BN=256 x BK=32, 512 threads.
// A fp32 [M,512] read ONCE. Register double-buffered.
__global__ __launch_bounds__(512) void f16_gemm1(
        const float* __restrict__ A, const float* __restrict__ B,
        __half* __restrict__ C, int M, int N, int K) {
    constexpr int BM = 128;
    constexpr int BN = 256;
    constexpr int BK = 32;
    constexpr int WM = 32;
    constexpr int WN = 64;
    constexpr int MFR = 2;
    constexpr int NFR = 8;
    constexpr int AS2 = 20;
    constexpr int BS2 = BN + 8;

    __shared__ __align__(16) __half2 As[BM][AS2];
    __shared__ __align__(16) __half2 Bs[BK / 2][BS2];

    const int tid  = threadIdx.x;
    const int warp = tid >> 5;
    const int lane = tid & 31;
    const int wm = (warp & 3) * WM;
    const int wn = (warp >> 2) * WN;
    const int rowBase = blockIdx.y * BM;

    float acc[MFR][NFR][4];
#pragma unroll
    for (int i = 0; i < MFR; i++)
#pragma unroll
        for (int j = 0; j < NFR; j++)
#pragma unroll
            for (int q = 0; q < 4; q++) acc[i][j][q] = 0.f;

    const int arow = tid >> 2;
    const int acol0 = (tid & 3) * 8;
    const int brow = tid >> 4;
    const int bf40 = tid & 15;
    const int gr = rowBase + arow;
    const bool aok = (gr < M);
    const float* aBase = A + (size_t)gr * K + acol0;
    const float* bBase = B + (size_t)brow * N;

    // --- prologue: prefetch k0 = 0 ---
    float4 pa0 = make_float4(0.f, 0.f, 0.f, 0.f);
    float4 pa1 = make_float4(0.f, 0.f, 0.f, 0.f);
    float4 pb[4];
    if (aok) { pa0 = *(const float4*)aBase; pa1 = *(const float4*)(aBase + 4); }
#pragma unroll
    for (int i = 0; i < 4; i++)
        pb[i] = *(const float4*)(bBase + (bf40 + i * 16) * 4);

    for (int k0 = 0; k0 < K; k0 += BK) {
        // --- store prefetched tile to smem (with f32->f16 conversion) ---
        {
            __half2 h[4];
            h[0] = __floats2half2_rn(pa0.x, pa0.y);
            h[1] = __floats2half2_rn(pa0.z, pa0.w);
            h[2] = __floats2half2_rn(pa1.x, pa1.y);
            h[3] = __floats2half2_rn(pa1.z, pa1.w);
            *(uint4*)&As[arow][acol0 / 2] = *(const uint4*)h;
        }
        {
            __half* bsh = (__half*)&Bs[brow >> 1][0];
            const int hsel = brow & 1;
#pragma unroll
            for (int i = 0; i < 4; i++) {
                const int n = (bf40 + i * 16) * 4;
                bsh[(n + 0) * 2 + hsel] = __float2half_rn(pb[i].x);
                bsh[(n + 1) * 2 + hsel] = __float2half_rn(pb[i].y);
                bsh[(n + 2) * 2 + hsel] = __float2half_rn(pb[i].z);
                bsh[(n + 3) * 2 + hsel] = __float2half_rn(pb[i].w);
            }
        }
        __syncthreads();

        // --- prefetch next tile (overlaps the MMA phase below) ---
        const int kn = k0 + BK;
        if (kn < K) {
            if (aok) {
                pa0 = *(const float4*)(aBase + kn);
                pa1 = *(const float4*)(aBase + kn + 4);
            }
            const float* bp = bBase + (size_t)kn * N;
#pragma unroll
            for (int i = 0; i < 4; i++)
                pb[i] = *(const float4*)(bp + (bf40 + i * 16) * 4);
        }

        // --- MMA phase ---
#pragma unroll
        for (int ks = 0; ks < BK / 16; ks++) {
            uint32_t afr[MFR][4];
            uint32_t bfr[NFR][2];
            const int ar = wm + (lane >> 2);
            const int kb = ks * 8 + (lane & 3);
#pragma unroll
            for (int mi = 0; mi < MFR; mi++) {
                afr[mi][0] = *(const uint32_t*)&As[ar + mi * 16 + 0][kb + 0];
                afr[mi][1] = *(const uint32_t*)&As[ar + mi * 16 + 8][kb + 0];
                afr[mi][2] = *(const uint32_t*)&As[ar + mi * 16 + 0][kb + 4];
                afr[mi][3] = *(const uint32_t*)&As[ar + mi * 16 + 8][kb + 4];
            }
            const int bc = wn + (lane >> 2);
#pragma unroll
            for (int ni = 0; ni < NFR; ni++) {
                bfr[ni][0] = *(const uint32_t*)&Bs[kb + 0][bc + ni * 8];
                bfr[ni][1] = *(const uint32_t*)&Bs[kb + 4][bc + ni * 8];
            }
#pragma unroll
            for (int mi = 0; mi < MFR; mi++)
#pragma unroll
                for (int ni = 0; ni < NFR; ni++)
                    mma_f16(acc[mi][ni], afr[mi], bfr[ni]);
        }
        __syncthreads();
    }

#pragma unroll
    for (int mi = 0; mi < MFR; mi++) {
#pragma unroll
        for (int ni = 0; ni < NFR; ni++) {
            const int r0 = rowBase + wm + mi * 16 + (lane >> 2);
            const int c0 = wn + ni * 8 + 2 * (lane & 3);
            if (r0 < M)
                *(__half2*)(C + (size_t)r0 * N + c0) =
                    __floats2half2_rn(acc[mi][ni][0], acc[mi][ni][1]);
            if (r0 + 8 < M)
                *(__half2*)(C + (size_t)(r0 + 8) * N + c0) =
                    __floats2half2_rn(acc[mi][ni][2], acc[mi][ni][3]);
        }
    }
}

// FP16 GEMM, fp16 A (direct copy), BM=128, BK=32, 256 threads. (GEMM2)
// Register double-buffered.
template<int BN, int WARPS_M, int WARPS_N>
__global__ __launch_bounds__(256) void f16_gemm_f16in(
        const __half* __restrict__ A, const float* __restrict__ B,
        __half* __restrict__ C, int M, int N, int K) {
    constexpr int BM = 128;
    constexpr int BK = 32;
    constexpr int WM = BM / WARPS_M;
    constexpr int WN = BN / WARPS_N;
    constexpr int MFR = WM / 16;
    constexpr int NFR = WN / 8;
    constexpr int AS2 = 20;
    constexpr int BS2 = BN + 8;

    __shared__ __align__(16) __half2 As[BM][AS2];
    __shared__ __align__(16) __half2 Bs[BK / 2][BS2];

    const int tid  = threadIdx.x;
    const int warp = tid >> 5;
    const int lane = tid & 31;
    const int wm = (warp % WARPS_M) * WM;
    const int wn = (warp / WARPS_M) * WN;
    const int rowBase = blockIdx.y * BM;
    const int colBase = blockIdx.x * BN;

    float acc[MFR][NFR][4];
#pragma unroll
    for (int i = 0; i < MFR; i++)
#pragma unroll
        for (int j = 0; j < NFR; j++)
#pragma unroll
            for (int q = 0; q < 4; q++) acc[i][j][q] = 0.f;

    const int arow = tid >> 1;
    const int acolh = (tid & 1) * 16;
    const int brow = tid >> 3;
    const int bf40 = tid & 7;
    const int gr = rowBase + arow;
    const bool aok = (gr < M);
    const __half* aBase = A + (size_t)gr * K + acolh;
    const float* bBase = B + (size_t)brow * N + colBase;

    // --- prologue: prefetch k0 = 0 ---
    uint4 pq0 = make_uint4(0, 0, 0, 0), pq1 = make_uint4(0, 0, 0, 0);
    float4 pb[BN / 32];
    if (aok) {
        pq0 = *(const uint4*)aBase;
        pq1 = *(const uint4*)(aBase + 8);
    }
#pragma unroll
    for (int i = 0; i < BN / 32; i++)
        pb[i] = *(const float4*)(bBase + (bf40 + i * 8) * 4);

    for (int k0 = 0; k0 < K; k0 += BK) {
        // --- store prefetched tile to smem ---
        *(uint4*)&As[arow][acolh / 2 + 0] = pq0;
        *(uint4*)&As[arow][acolh / 2 + 4] = pq1;
        {
            __half* bsh = (__half*)&Bs[brow >> 1][0];
            const int hsel = brow & 1;
#pragma unroll
            for (int i = 0; i < BN / 32; i++) {
                const int n = (bf40 + i * 8) * 4;
                bsh[(n + 0) * 2 + hsel] = __float2half_rn(pb[i].x);
                bsh[(n + 1) * 2 + hsel] = __float2half_rn(pb[i].y);
                bsh[(n + 2) * 2 + hsel] = __float2half_rn(pb[i].z);
                bsh[(n + 3) * 2 + hsel] = __float2half_rn(pb[i].w);
            }
        }
        __syncthreads();

        // --- prefetch next tile (overlaps MMA phase) ---
        const int kn = k0 + BK;
        if (kn < K) {
            if (aok) {
                pq0 = *(const uint4*)(aBase + kn);
                pq1 = *(const uint4*)(aBase + kn + 8);
            }
            const float* bp = bBase + (size_t)kn * N;
#pragma unroll
            for (int i = 0; i < BN / 32; i++)
                pb[i] = *(const float4*)(bp + (bf40 + i * 8) * 4);
        }

        // --- MMA phase ---
#pragma unroll
        for (int ks = 0; ks < BK / 16; ks++) {
            uint32_t afr[MFR][4];
            uint32_t bfr[NFR][2];
            const int ar = wm + (lane >> 2);
            const int kb = ks * 8 + (lane & 3);
#pragma unroll
            for (int mi = 0; mi < MFR; mi++) {
                afr[mi][0] = *(const uint32_t*)&As[ar + mi * 16 + 0][kb + 0];
                afr[mi][1] = *(const uint32_t*)&As[ar + mi * 16 + 8][kb + 0];
                afr[mi][2] = *(const uint32_t*)&As[ar + mi * 16 + 0][kb + 4];
                afr[mi][3] = *(const uint32_t*)&As[ar + mi * 16 + 8][kb + 4];
            }
            const int bc = wn + (lane >> 2);
#pragma unroll
            for (int ni = 0; ni < NFR; ni++) {
                bfr[ni][0] = *(const uint32_t*)&Bs[kb + 0][bc + ni * 8];
                bfr[ni][1] = *(const uint32_t*)&Bs[kb + 4][bc + ni * 8];
            }
#pragma unroll
            for (int mi = 0; mi < MFR; mi++)
#pragma unroll
                for (int ni = 0; ni < NFR; ni++)
                    mma_f16(acc[mi][ni], afr[mi], bfr[ni]);
        }
        __syncthreads();
    }

#pragma unroll
    for (int mi = 0; mi < MFR; mi++) {
#pragma unroll
        for (int ni = 0; ni < NFR; ni++) {
            const int r0 = rowBase + wm + mi * 16 + (lane >> 2);
            const int c0 = colBase + wn + ni * 8 + 2 * (lane & 3);
            if (r0 < M)
                *(__half2*)(C + (size_t)r0 * N + c0) =
                    __floats2half2_rn(acc[mi][ni][0], acc[mi][ni][1]);
            if (r0 + 8 < M)
                *(__half2*)(C + (size_t)(r0 + 8) * N + c0) =
                    __floats2half2_rn(acc[mi][ni][2], acc[mi][ni][3]);
        }
    }
}

// ---------------------------------------------------------------------------
// CSR SpMM, F=256, fp16 source (R7 inner-loop form, bucketed edges).
// One warp per row; lane owns 8 halfs.
__global__ void spmm_csr_f256h(const __half* __restrict__ X, const float* __restrict__ bias,
                               __half* __restrict__ Y) {
    const int r = (blockIdx.x * blockDim.x + threadIdx.x) >> 5;
    const int lane = threadIdx.x & 31;
    if (r >= NNODE) return;
    const int cnt = g_cursor[r];
    const int2* erow = g_edges + (size_t)r * SLOT;
    float acc[8];
#pragma unroll
    for (int i = 0; i < 8; i++) acc[i] = 0.f;
    const uint4* Xb = (const uint4*)X + lane;
    for (int base = 0; base < cnt; base += 32) {
        const int m = min(32, cnt - base);
        int2 ev = make_int2(0, 0);
        if (lane < m) ev = erow[base + lane];
#pragma unroll 4
        for (int j = 0; j < m; j++) {
            const int   cj = __shfl_sync(0xffffffffu, ev.x, j);
            const float vj = __int_as_float(__shfl_sync(0xffffffffu, ev.y, j));
            uint4 q = __ldg(Xb + (size_t)cj * 32);
            const __half2* hp = (const __half2*)&q;
#pragma unroll
            for (int i = 0; i < 4; i++) {
                float2 f = __half22float2(hp[i]);
                acc[i * 2 + 0] = fmaf(vj, f.x, acc[i * 2 + 0]);
                acc[i * 2 + 1] = fmaf(vj, f.y, acc[i * 2 + 1]);
            }
        }
    }
    float4 b0 = __ldg((const float4*)bias + lane * 2);
    float4 b1 = __ldg((const float4*)bias + lane * 2 + 1);
    float bb[8] = {b0.x, b0.y, b0.z, b0.w, b1.x, b1.y, b1.z, b1.w};
    __half2 o[4];
#pragma unroll
    for (int i = 0; i < 4; i++)
        o[i] = __floats2half2_rn(fmaxf(acc[i * 2] + bb[i * 2], 0.f),
                                 fmaxf(acc[i * 2 + 1] + bb[i * 2 + 1], 0.f));
    uint4 ov = *(const uint4*)o;
    stcs_u4((uint4*)Y + (size_t)r * 32 + lane, ov);
}

// CSR SpMM F=64 (fp16 source) fused with bias + log_softmax (bucketed edges).
__global__ void spmm_csr_f64h_ls(const __half* __restrict__ X, const float* __restrict__ bias,
                                 float* __restrict__ out) {
    const int r = (blockIdx.x * blockDim.x + threadIdx.x) >> 5;
    const int lane = threadIdx.x & 31;
    if (r >= NNODE) return;
    const int cnt = g_cursor[r];
    const int2* erow = g_edges + (size_t)r * SLOT;
    float2 acc = make_float2(0.f, 0.f);
    const uint32_t* Xb = (const uint32_t*)X + lane;
    for (int base = 0; base < cnt; base += 32) {
        const int m = min(32, cnt - base);
        int2 ev = make_int2(0, 0);
        if (lane < m) ev = erow[base + lane];
#pragma unroll 4
        for (int j = 0; j < m; j++) {
            const int   cj = __shfl_sync(0xffffffffu, ev.x, j);
            const float vj = __int_as_float(__shfl_sync(0xffffffffu, ev.y, j));
            uint32_t q = __ldg(Xb + (size_t)cj * 32);
            float2 xs = __half22float2(*(const __half2*)&q);
            acc.x = fmaf(vj, xs.x, acc.x);
            acc.y = fmaf(vj, xs.y, acc.y);
        }
    }
    float2 bb = __ldg((const float2*)bias + lane);
    float v0 = acc.x + bb.x;
    float v1 = acc.y + bb.y;
    float mx = fmaxf(v0, v1);
#pragma unroll
    for (int o = 16; o; o >>= 1) mx = fmaxf(mx, __shfl_xor_sync(0xffffffffu, mx, o));
    float s = __expf(v0 - mx) + __expf(v1 - mx);
#pragma unroll
    for (int o = 16; o; o >>= 1) s += __shfl_xor_sync(0xffffffffu, s, o);
    float lse = mx + __logf(s);
    *(float2*)(out + (size_t)r * 64 + lane * 2) = make_float2(v0 - lse, v1 - lse);
}

// ---------------------------------------------------------------------------
extern "C" void kernel_launch(void* const* d_in, const int* in_sizes, int n_in,
                              void* d_out, int out_size) {
    const float* x    = (const float*)d_in[0];
    const int*   erow = (const int*)d_in[1];
    const int*   ecol = (const int*)d_in[2];
    const float* eval_ = (const float*)d_in[3];
    const float* W1   = (const float*)d_in[4];
    const float* b1   = (const float*)d_in[5];
    const float* W2   = (const float*)d_in[6];
    const float* b2   = (const float*)d_in[7];
    float* out = (float*)d_out;

    const int E = in_sizes[1];
    const int M = in_sizes[0] / NF;  // 100000

    __half *xw1, *h, *hw2;
    cudaGetSymbolAddress((void**)&xw1, g_xw1);
    cudaGetSymbolAddress((void**)&h, g_h);
    cudaGetSymbolAddress((void**)&hw2, g_hw2);

    // One-time side resources (host-side only; no device memory involved).
    static cudaStream_t s2 = nullptr;
    static cudaEvent_t evFork = nullptr, evJoin = nullptr;
    if (!s2) {
        cudaStreamCreateWithFlags(&s2, cudaStreamNonBlocking);
        cudaEventCreateWithFlags(&evFork, cudaEventDisableTiming);
        cudaEventCreateWithFlags(&evJoin, cudaEventDisableTiming);
    }

    // Fork: edge-bucket build on s2, concurrent with GEMM1 on the main stream.
    cudaEventRecord(evFork, 0);
    cudaStreamWaitEvent(s2, evFork, 0);

    // --- bucketed edge build (stream s2): zero + single scatter pass ---
    k_zero_cnt<<<(NNODE + 255) / 256, 256, 0, s2>>>();
    k_scatter_direct<<<(E + 255) / 256, 256, 0, s2>>>(erow, ecol, eval_, E);
    cudaEventRecord(evJoin, s2);

    // --- layer 1 GEMM (main stream, concurrent with edge build) ---
    f16_gemm1<<<dim3(1, (M + 127) / 128), 512>>>(x, W1, xw1, M, NH, NF);

    // Join: spmm1 needs both GEMM1 and the edge buckets.
    cudaStreamWaitEvent(0, evJoin, 0);

    // spmm1 (bucketed gather, fp16 source L2-resident) + fused bias/relu
    {
        int blocks = (NNODE * 32 + 255) / 256;
        spmm_csr_f256h<<<blocks, 256>>>(xw1, b1, h);
    }

    // layer 2: HW2 = h @ W2  (fp16 tensor cores, fp16 A direct)
    f16_gemm_f16in<64, 4, 2><<<dim3(NC / 64, (M + 127) / 128), 256>>>(h, W2, hw2, M, NC, NH);

    // spmm2 (bucketed gather, fp16 source) + fused bias + log_softmax
    {
        int blocks = (NNODE * 32 + 255) / 256;
        spmm_csr_f64h_ls<<<blocks, 256>>>(hw2, b2, out);
    }
}

// round 14
// speedup vs baseline: 1.0078x; 1.0078x over previous
#include <cuda_runtime.h>
#include <cuda_fp16.h>
#include <cstdint>

// Problem constants (shapes fixed by the reference)
constexpr int NF = 512;   // input features
constexpr int NH = 256;   // hidden
constexpr int NC = 64;    // classes
constexpr int NNODE = 100000;
constexpr int EMAX = 3200000;

// Scratch (allocation-free rule: __device__ globals)
__device__ __half g_xw1[(size_t)NNODE * NH];  // x @ W1 (fp16)
__device__ __half g_h[(size_t)NNODE * NH];    // spmm1 out / h (fp16)
__device__ __half g_hw2[(size_t)NNODE * NC];  // h @ W2 (fp16)
__device__ int    g_rowptr[NNODE + 1];
__device__ int    g_cursor[NNODE];
__device__ int2   g_edges[EMAX];              // (col, val-bits) sorted by row
__device__ int    g_bsums[128];

// ---------------------------------------------------------------------------
__device__ __forceinline__ void mma_f16(float c[4], const uint32_t a[4], const uint32_t b[2]) {
    asm volatile(
        "mma.sync.aligned.m16n8k16.row.col.f32.f16.f16.f32 "
        "{%0,%1,%2,%3}, {%4,%5,%6,%7}, {%8,%9}, {%0,%1,%2,%3};"
        : "+f"(c[0]), "+f"(c[1]), "+f"(c[2]), "+f"(c[3])
        : "r"(a[0]), "r"(a[1]), "r"(a[2]), "r"(a[3]), "r"(b[0]), "r"(b[1]));
}

__device__ __forceinline__ void ldsm_x4(uint32_t r[4], uint32_t saddr) {
    asm volatile("ldmatrix.sync.aligned.m8n8.x4.shared.b16 {%0,%1,%2,%3}, [%4];"
                 : "=r"(r[0]), "=r"(r[1]), "=r"(r[2]), "=r"(r[3]) : "r"(saddr));
}

__device__ __forceinline__ void stcs_u4(uint4* p, uint4 v) {
    asm volatile("st.global.cs.v4.u32 [%0], {%1,%2,%3,%4};"
                 :: "l"(p), "r"(v.x), "r"(v.y), "r"(v.z), "r"(v.w) : "memory");
}

// half2 -> f32x2 convert + packed fma into a packed f32x2 accumulator
__device__ __forceinline__ void h2fma(uint64_t& acc, uint32_t h2, uint64_t vv) {
    asm("{\n\t"
        ".reg .f16 alo, ahi;\n\t"
        ".reg .f32 flo, fhi;\n\t"
        ".reg .b64 ff;\n\t"
        "mov.b32 {alo, ahi}, %1;\n\t"
        "cvt.f32.f16 flo, alo;\n\t"
        "cvt.f32.f16 fhi, ahi;\n\t"
        "mov.b64 ff, {flo, fhi};\n\t"
        "fma.rn.f32x2 %0, ff, %2, %0;\n\t"
        "}" : "+l"(acc) : "r"(h2), "l"(vv));
}

__device__ __forceinline__ uint64_t pack2(float v) {
    uint64_t r;
    asm("mov.b64 %0, {%1, %1};" : "=l"(r) : "f"(v));
    return r;
}

__device__ __forceinline__ float2 unpack2(uint64_t v) {
    float2 f;
    asm("mov.b64 {%0, %1}, %2;" : "=f"(f.x), "=f"(f.y) : "l"(v));
    return f;
}

// ---------------------------------------------------------------------------
// CSR build
__global__ void k_zero_csr() {
    int i = blockIdx.x * blockDim.x + threadIdx.x;
    if (i <= NNODE) g_rowptr[i] = 0;
    if (i < NNODE) g_cursor[i] = 0;
}

__global__ void k_hist(const int* __restrict__ rows, int E) {
    int e = blockIdx.x * blockDim.x + threadIdx.x;
    if (e < E) atomicAdd(&g_rowptr[rows[e] + 1], 1);
}

// inclusive block scan: 1024 elements per block (256 threads x 4)
__global__ void k_scan_block(int* __restrict__ d, int L, int* __restrict__ bsums) {
    __shared__ int warpsum[8];
    const int t = threadIdx.x, lane = t & 31, wid = t >> 5;
    const int base = blockIdx.x * 1024 + t * 4;
    int v0 = 0, v1 = 0, v2 = 0, v3 = 0;
    if (base + 3 < L) {
        int4 x = *(const int4*)(d + base);
        v0 = x.x; v1 = x.y; v2 = x.z; v3 = x.w;
    } else {
        if (base < L) v0 = d[base];
        if (base + 1 < L) v1 = d[base + 1];
        if (base + 2 < L) v2 = d[base + 2];
    }
    v1 += v0; v2 += v1; v3 += v2;
    int inc = v3;
#pragma unroll
    for (int o = 1; o < 32; o <<= 1) {
        int n = __shfl_up_sync(0xffffffffu, inc, o);
        if (lane >= o) inc += n;
    }
    if (lane == 31) warpsum[wid] = inc;
    __syncthreads();
    if (wid == 0) {
        int s = (lane < 8) ? warpsum[lane] : 0;
#pragma unroll
        for (int o = 1; o < 8; o <<= 1) {
            int n = __shfl_up_sync(0xffffffffu, s, o);
            if (lane >= o) s += n;
        }
        if (lane < 8) warpsum[lane] = s;
    }
    __syncthreads();
    int off = inc - v3;
    if (wid > 0) off += warpsum[wid - 1];
    v0 += off; v1 += off; v2 += off; v3 += off;
    if (base + 3 < L) {
        *(int4*)(d + base) = make_int4(v0, v1, v2, v3);
    } else {
        if (base < L) d[base] = v0;
        if (base + 1 < L) d[base + 1] = v1;
        if (base + 2 < L) d[base + 2] = v2;
    }
    if (t == 255) bsums[blockIdx.x] = v3;
}

__global__ void k_scan_sums(int* __restrict__ bsums, int nb) {
    __shared__ int ws[4];
    const int t = threadIdx.x, lane = t & 31, wid = t >> 5;
    int v = (t < nb) ? bsums[t] : 0;
    int inc = v;
#pragma unroll
    for (int o = 1; o < 32; o <<= 1) {
        int n = __shfl_up_sync(0xffffffffu, inc, o);
        if (lane >= o) inc += n;
    }
    if (lane == 31) ws[wid] = inc;
    __syncthreads();
    if (t == 0) {
        int run = 0;
#pragma unroll
        for (int i = 0; i < 4; i++) { int tmp = ws[i]; ws[i] = run; run += tmp; }
    }
    __syncthreads();
    int excl = inc - v + ws[wid];
    if (t < nb) bsums[t] = excl;
}

__global__ void k_scan_add(int* __restrict__ d, int L) {
    const int b = blockIdx.x;
    if (b == 0) return;
    const int add = g_bsums[b];
    const int base = b * 1024 + threadIdx.x * 4;
#pragma unroll
    for (int j = 0; j < 4; j++)
        if (base + j < L) d[base + j] += add;
}

__global__ void k_scatter(const int* __restrict__ rows, const int* __restrict__ cols,
                          const float* __restrict__ vals, int E) {
    int e = blockIdx.x * blockDim.x + threadIdx.x;
    if (e >= E) return;
    int r = rows[e];
    int idx = g_rowptr[r] + atomicAdd(&g_cursor[r], 1);
    g_edges[idx] = make_int2(cols[e], __float_as_int(vals[e]));
}

// ---------------------------------------------------------------------------
// FP16 GEMM (m16n8k16, fp32 accum), BM=128 x BN=256 x BK=32, 512 threads.
// A fp32 [M,512] read ONCE. Register double-buffered; A-frags via ldmatrix.
__global__ __launch_bounds__(512) void f16_gemm1(
        const float* __restrict__ A, const float* __restrict__ B,
        __half* __restrict__ C, int M, int N, int K) {
    constexpr int BM = 128;
    constexpr int BN = 256;
    constexpr int BK = 32;
    constexpr int WM = 32;
    constexpr int WN = 64;
    constexpr int MFR = 2;
    constexpr int NFR = 8;
    constexpr int AS2 = 20;
    constexpr int BS2 = BN + 8;

    __shared__ __align__(16) __half2 As[BM][AS2];
    __shared__ __align__(16) __half2 Bs[BK / 2][BS2];

    const int tid  = threadIdx.x;
    const int warp = tid >> 5;
    const int lane = tid & 31;
    const int wm = (warp & 3) * WM;
    const int wn = (warp >> 2) * WN;
    const int rowBase = blockIdx.y * BM;

    float acc[MFR][NFR][4];
#pragma unroll
    for (int i = 0; i < MFR; i++)
#pragma unroll
        for (int j = 0; j < NFR; j++)
#pragma unroll
            for (int q = 0; q < 4; q++) acc[i][j][q] = 0.f;

    const int arow = tid >> 2;
    const int acol0 = (tid & 3) * 8;
    const int brow = tid >> 4;
    const int bf40 = tid & 15;
    const int gr = rowBase + arow;
    const bool aok = (gr < M);
    const float* aBase = A + (size_t)gr * K + acol0;
    const float* bBase = B + (size_t)brow * N;

    // ldmatrix per-lane source row/col (within warp tile)
    const int lmRow = (lane & 7) + ((lane >> 3) & 1) * 8;
    const int lmK2  = (lane >> 4) * 4;  // half2 offset: k + 0 or k + 8 halfs

    // --- prologue: prefetch k0 = 0 ---
    float4 pa0 = make_float4(0.f, 0.f, 0.f, 0.f);
    float4 pa1 = make_float4(0.f, 0.f, 0.f, 0.f);
    float4 pb[4];
    if (aok) { pa0 = *(const float4*)aBase; pa1 = *(const float4*)(aBase + 4); }
#pragma unroll
    for (int i = 0; i < 4; i++)
        pb[i] = *(const float4*)(bBase + (bf40 + i * 16) * 4);

    for (int k0 = 0; k0 < K; k0 += BK) {
        {
            __half2 h[4];
            h[0] = __floats2half2_rn(pa0.x, pa0.y);
            h[1] = __floats2half2_rn(pa0.z, pa0.w);
            h[2] = __floats2half2_rn(pa1.x, pa1.y);
            h[3] = __floats2half2_rn(pa1.z, pa1.w);
            *(uint4*)&As[arow][acol0 / 2] = *(const uint4*)h;
        }
        {
            __half* bsh = (__half*)&Bs[brow >> 1][0];
            const int hsel = brow & 1;
#pragma unroll
            for (int i = 0; i < 4; i++) {
                const int n = (bf40 + i * 16) * 4;
                bsh[(n + 0) * 2 + hsel] = __float2half_rn(pb[i].x);
                bsh[(n + 1) * 2 + hsel] = __float2half_rn(pb[i].y);
                bsh[(n + 2) * 2 + hsel] = __float2half_rn(pb[i].z);
                bsh[(n + 3) * 2 + hsel] = __float2half_rn(pb[i].w);
            }
        }
        __syncthreads();

        const int kn = k0 + BK;
        if (kn < K) {
            if (aok) {
                pa0 = *(const float4*)(aBase + kn);
                pa1 = *(const float4*)(aBase + kn + 4);
            }
            const float* bp = bBase + (size_t)kn * N;
#pragma unroll
            for (int i = 0; i < 4; i++)
                pb[i] = *(const float4*)(bp + (bf40 + i * 16) * 4);
        }

#pragma unroll
        for (int ks = 0; ks < BK / 16; ks++) {
            uint32_t afr[MFR][4];
            uint32_t bfr[NFR][2];
#pragma unroll
            for (int mi = 0; mi < MFR; mi++) {
                uint32_t saddr = (uint32_t)__cvta_generic_to_shared(
                    &As[wm + mi * 16 + lmRow][ks * 8 + lmK2]);
                ldsm_x4(afr[mi], saddr);
            }
            const int kb = ks * 8 + (lane & 3);
            const int bc = wn + (lane >> 2);
#pragma unroll
            for (int ni = 0; ni < NFR; ni++) {
                bfr[ni][0] = *(const uint32_t*)&Bs[kb + 0][bc + ni * 8];
                bfr[ni][1] = *(const uint32_t*)&Bs[kb + 4][bc + ni * 8];
            }
#pragma unroll
            for (int mi = 0; mi < MFR; mi++)
#pragma unroll
                for (int ni = 0; ni < NFR; ni++)
                    mma_f16(acc[mi][ni], afr[mi], bfr[ni]);
        }
        __syncthreads();
    }

#pragma unroll
    for (int mi = 0; mi < MFR; mi++) {
#pragma unroll
        for (int ni = 0; ni < NFR; ni++) {
            const int r0 = rowBase + wm + mi * 16 + (lane >> 2);
            const int c0 = wn + ni * 8 + 2 * (lane & 3);
            if (r0 < M)
                *(__half2*)(C + (size_t)r0 * N + c0) =
                    __floats2half2_rn(acc[mi][ni][0], acc[mi][ni][1]);
            if (r0 + 8 < M)
                *(__half2*)(C + (size_t)(r0 + 8) * N + c0) =
                    __floats2half2_rn(acc[mi][ni][2], acc[mi][ni][3]);
        }
    }
}

// FP16 GEMM, fp16 A (direct copy), BM=128, BK=32, 256 threads. (GEMM2)
// Register double-buffered; A-frags via ldmatrix.
template<int BN, int WARPS_M, int WARPS_N>
__global__ __launch_bounds__(256) void f16_gemm_f16in(
        const __half* __restrict__ A, const float* __restrict__ B,
        __half* __restrict__ C, int M, int N, int K) {
    constexpr int BM = 128;
    constexpr int BK = 32;
    constexpr int WM = BM / WARPS_M;
    constexpr int WN = BN / WARPS_N;
    constexpr int MFR = WM / 16;
    constexpr int NFR = WN / 8;
    constexpr int AS2 = 20;
    constexpr int BS2 = BN + 8;

    __shared__ __align__(16) __half2 As[BM][AS2];
    __shared__ __align__(16) __half2 Bs[BK / 2][BS2];

    const int tid  = threadIdx.x;
    const int warp = tid >> 5;
    const int lane = tid & 31;
    const int wm = (warp % WARPS_M) * WM;
    const int wn = (warp / WARPS_M) * WN;
    const int rowBase = blockIdx.y * BM;
    const int colBase = blockIdx.x * BN;

    float acc[MFR][NFR][4];
#pragma unroll
    for (int i = 0; i < MFR; i++)
#pragma unroll
        for (int j = 0; j < NFR; j++)
#pragma unroll
            for (int q = 0; q < 4; q++) acc[i][j][q] = 0.f;

    const int arow = tid >> 1;
    const int acolh = (tid & 1) * 16;
    const int brow = tid >> 3;
    const int bf40 = tid & 7;
    const int gr = rowBase + arow;
    const bool aok = (gr < M);
    const __half* aBase = A + (size_t)gr * K + acolh;
    const float* bBase = B + (size_t)brow * N + colBase;

    const int lmRow = (lane & 7) + ((lane >> 3) & 1) * 8;
    const int lmK2  = (lane >> 4) * 4;

    uint4 pq0 = make_uint4(0, 0, 0, 0), pq1 = make_uint4(0, 0, 0, 0);
    float4 pb[BN / 32];
    if (aok) {
        pq0 = *(const uint4*)aBase;
        pq1 = *(const uint4*)(aBase + 8);
    }
#pragma unroll
    for (int i = 0; i < BN / 32; i++)
        pb[i] = *(const float4*)(bBase + (bf40 + i * 8) * 4);

    for (int k0 = 0; k0 < K; k0 += BK) {
        *(uint4*)&As[arow][acolh / 2 + 0] = pq0;
        *(uint4*)&As[arow][acolh / 2 + 4] = pq1;
        {
            __half* bsh = (__half*)&Bs[brow >> 1][0];
            const int hsel = brow & 1;
#pragma unroll
            for (int i = 0; i < BN / 32; i++) {
                const int n = (bf40 + i * 8) * 4;
                bsh[(n + 0) * 2 + hsel] = __float2half_rn(pb[i].x);
                bsh[(n + 1) * 2 + hsel] = __float2half_rn(pb[i].y);
                bsh[(n + 2) * 2 + hsel] = __float2half_rn(pb[i].z);
                bsh[(n + 3) * 2 + hsel] = __float2half_rn(pb[i].w);
            }
        }
        __syncthreads();

        const int kn = k0 + BK;
        if (kn < K) {
            if (aok) {
                pq0 = *(const uint4*)(aBase + kn);
                pq1 = *(const uint4*)(aBase + kn + 8);
            }
            const float* bp = bBase + (size_t)kn * N;
#pragma unroll
            for (int i = 0; i < BN / 32; i++)
                pb[i] = *(const float4*)(bp + (bf40 + i * 8) * 4);
        }

#pragma unroll
        for (int ks = 0; ks < BK / 16; ks++) {
            uint32_t afr[MFR][4];
            uint32_t bfr[NFR][2];
#pragma unroll
            for (int mi = 0; mi < MFR; mi++) {
                uint32_t saddr = (uint32_t)__cvta_generic_to_shared(
                    &As[wm + mi * 16 + lmRow][ks * 8 + lmK2]);
                ldsm_x4(afr[mi], saddr);
            }
            const int kb = ks * 8 + (lane & 3);
            const int bc = wn + (lane >> 2);
#pragma unroll
            for (int ni = 0; ni < NFR; ni++) {
                bfr[ni][0] = *(const uint32_t*)&Bs[kb + 0][bc + ni * 8];
                bfr[ni][1] = *(const uint32_t*)&Bs[kb + 4][bc + ni * 8];
            }
#pragma unroll
            for (int mi = 0; mi < MFR; mi++)
#pragma unroll
                for (int ni = 0; ni < NFR; ni++)
                    mma_f16(acc[mi][ni], afr[mi], bfr[ni]);
        }
        __syncthreads();
    }

#pragma unroll
    for (int mi = 0; mi < MFR; mi++) {
#pragma unroll
        for (int ni = 0; ni < NFR; ni++) {
            const int r0 = rowBase + wm + mi * 16 + (lane >> 2);
            const int c0 = colBase + wn + ni * 8 + 2 * (lane & 3);
            if (r0 < M)
                *(__half2*)(C + (size_t)r0 * N + c0) =
                    __floats2half2_rn(acc[mi][ni][0], acc[mi][ni][1]);
            if (r0 + 8 < M)
                *(__half2*)(C + (size_t)(r0 + 8) * N + c0) =
                    __floats2half2_rn(acc[mi][ni][2], acc[mi][ni][3]);
        }
    }
}

// ---------------------------------------------------------------------------
// CSR SpMM, F=256, fp16 source (R7/R12 structure). One warp per row; lane owns
// 8 halfs. Packed f32x2 accumulation (FFMA2) to cut issue count.
__global__ void spmm_csr_f256h(const __half* __restrict__ X, const float* __restrict__ bias,
                               __half* __restrict__ Y) {
    const int r = (blockIdx.x * blockDim.x + threadIdx.x) >> 5;
    const int lane = threadIdx.x & 31;
    if (r >= NNODE) return;
    const int start = g_rowptr[r];
    const int end   = g_rowptr[r + 1];
    uint64_t acc2[4] = {0ull, 0ull, 0ull, 0ull};  // 4x packed f32x2
    const uint4* Xb = (const uint4*)X + lane;
    for (int base = start; base < end; base += 32) {
        const int m = min(32, end - base);
        int2 ev = make_int2(0, 0);
        if (lane < m) ev = g_edges[base + lane];
#pragma unroll 4
        for (int j = 0; j < m; j++) {
            const int   cj = __shfl_sync(0xffffffffu, ev.x, j);
            const float vj = __int_as_float(__shfl_sync(0xffffffffu, ev.y, j));
            const uint64_t vv = pack2(vj);
            uint4 q = __ldg(Xb + (size_t)cj * 32);
            h2fma(acc2[0], q.x, vv);
            h2fma(acc2[1], q.y, vv);
            h2fma(acc2[2], q.z, vv);
            h2fma(acc2[3], q.w, vv);
        }
    }
    float4 b0 = __ldg((const float4*)bias + lane * 2);
    float4 b1 = __ldg((const float4*)bias + lane * 2 + 1);
    float bb[8] = {b0.x, b0.y, b0.z, b0.w, b1.x, b1.y, b1.z, b1.w};
    __half2 o[4];
#pragma unroll
    for (int i = 0; i < 4; i++) {
        float2 f = unpack2(acc2[i]);
        o[i] = __floats2half2_rn(fmaxf(f.x + bb[i * 2], 0.f),
                                 fmaxf(f.y + bb[i * 2 + 1], 0.f));
    }
    uint4 ov = *(const uint4*)o;
    stcs_u4((uint4*)Y + (size_t)r * 32 + lane, ov);
}

// CSR SpMM F=64 (fp16 source) fused with bias + log_softmax; packed FFMA2.
__global__ void spmm_csr_f64h_ls(const __half* __restrict__ X, const float* __restrict__ bias,
                                 float* __restrict__ out) {
    const int r = (blockIdx.x * blockDim.x + threadIdx.x) >> 5;
    const int lane = threadIdx.x & 31;
    if (r >= NNODE) return;
    const int start = g_rowptr[r];
    const int end   = g_rowptr[r + 1];
    uint64_t acc2 = 0ull;
    const uint32_t* Xb = (const uint32_t*)X + lane;
    for (int base = start; base < end; base += 32) {
        const int m = min(32, end - base);
        int2 ev = make_int2(0, 0);
        if (lane < m) ev = g_edges[base + lane];
#pragma unroll 4
        for (int j = 0; j < m; j++) {
            const int   cj = __shfl_sync(0xffffffffu, ev.x, j);
            const float vj = __int_as_float(__shfl_sync(0xffffffffu, ev.y, j));
            const uint64_t vv = pack2(vj);
            uint32_t q = __ldg(Xb + (size_t)cj * 32);
            h2fma(acc2, q, vv);
        }
    }
    float2 acc = unpack2(acc2);
    float2 bb = __ldg((const float2*)bias + lane);
    float v0 = acc.x + bb.x;
    float v1 = acc.y + bb.y;
    float mx = fmaxf(v0, v1);
#pragma unroll
    for (int o = 16; o; o >>= 1) mx = fmaxf(mx, __shfl_xor_sync(0xffffffffu, mx, o));
    float s = __expf(v0 - mx) + __expf(v1 - mx);
#pragma unroll
    for (int o = 16; o; o >>= 1) s += __shfl_xor_sync(0xffffffffu, s, o);
    float lse = mx + __logf(s);
    *(float2*)(out + (size_t)r * 64 + lane * 2) = make_float2(v0 - lse, v1 - lse);
}

// ---------------------------------------------------------------------------
extern "C" void kernel_launch(void* const* d_in, const int* in_sizes, int n_in,
                              void* d_out, int out_size) {
    const float* x    = (const float*)d_in[0];
    const int*   erow = (const int*)d_in[1];
    const int*   ecol = (const int*)d_in[2];
    const float* eval_ = (const float*)d_in[3];
    const float* W1   = (const float*)d_in[4];
    const float* b1   = (const float*)d_in[5];
    const float* W2   = (const float*)d_in[6];
    const float* b2   = (const float*)d_in[7];
    float* out = (float*)d_out;

    const int E = in_sizes[1];
    const int M = in_sizes[0] / NF;  // 100000

    __half *xw1, *h, *hw2;
    int *rowptr, *bsums;
    cudaGetSymbolAddress((void**)&xw1, g_xw1);
    cudaGetSymbolAddress((void**)&h, g_h);
    cudaGetSymbolAddress((void**)&hw2, g_hw2);
    cudaGetSymbolAddress((void**)&rowptr, g_rowptr);
    cudaGetSymbolAddress((void**)&bsums, g_bsums);

    const int L = NNODE + 1;
    const int nscan = (L + 1023) / 1024;  // 98

    // One-time side resources (host-side only; no device memory involved).
    static cudaStream_t s2 = nullptr;
    static cudaEvent_t evFork = nullptr, evJoin = nullptr;
    if (!s2) {
        cudaStreamCreateWithFlags(&s2, cudaStreamNonBlocking);
        cudaEventCreateWithFlags(&evFork, cudaEventDisableTiming);
        cudaEventCreateWithFlags(&evJoin, cudaEventDisableTiming);
    }

    // Fork: CSR build on s2, concurrent with GEMM1 on the main stream.
    cudaEventRecord(evFork, 0);
    cudaStreamWaitEvent(s2, evFork, 0);

    // --- CSR build (stream s2) ---
    k_zero_csr<<<(NNODE + 256) / 256, 256, 0, s2>>>();
    k_hist<<<(E + 255) / 256, 256, 0, s2>>>(erow, E);
    k_scan_block<<<nscan, 256, 0, s2>>>(rowptr, L, bsums);
    k_scan_sums<<<1, 128, 0, s2>>>(bsums, nscan);
    k_scan_add<<<nscan, 256, 0, s2>>>(rowptr, L);
    k_scatter<<<(E + 255) / 256, 256, 0, s2>>>(erow, ecol, eval_, E);
    cudaEventRecord(evJoin, s2);

    // --- layer 1 GEMM (main stream, concurrent with CSR build) ---
    f16_gemm1<<<dim3(1, (M + 127) / 128), 512>>>(x, W1, xw1, M, NH, NF);

    // Join: spmm1 needs both GEMM1 and the CSR structures.
    cudaStreamWaitEvent(0, evJoin, 0);

    // spmm1 (CSR gather, fp16 source L2-resident) + fused bias/relu
    {
        int blocks = (NNODE * 32 + 255) / 256;
        spmm_csr_f256h<<<blocks, 256>>>(xw1, b1, h);
    }

    // layer 2: HW2 = h @ W2  (fp16 tensor cores, fp16 A direct)
    f16_gemm_f16in<64, 4, 2><<<dim3(NC / 64, (M + 127) / 128), 256>>>(h, W2, hw2, M, NC, NH);

    // spmm2 (CSR gather, fp16 source) + fused bias + log_softmax
    {
        int blocks = (NNODE * 32 + 255) / 256;
        spmm_csr_f64h_ls<<<blocks, 256>>>(hw2, b2, out);
    }
}

// round 15
// speedup vs baseline: 1.0621x; 1.0539x over previous
#include <cuda_runtime.h>
#include <cuda_fp16.h>
#include <cstdint>

// Problem constants (shapes fixed by the reference)
constexpr int NF = 512;   // input features
constexpr int NH = 256;   // hidden
constexpr int NC = 64;    // classes
constexpr int NNODE = 100000;
constexpr int EMAX = 3200000;

// Scratch (allocation-free rule: __device__ globals)
__device__ __half   g_xw1[(size_t)NNODE * NH];  // x @ W1 (fp16)
__device__ __half   g_h[(size_t)NNODE * NH];    // spmm1 out / h (fp16)
__device__ __half   g_hw2[(size_t)NNODE * NC];  // h @ W2 (fp16)
__device__ int      g_rowptr[NNODE + 1];
__device__ int      g_cursor[NNODE];
__device__ int2     g_edges[EMAX];              // (col, val-bits) sorted by row
__device__ int      g_bsums[128];
// Pre-converted weights, k-pair interleaved: [k2][n] = half2(W[2k2][n], W[2k2+1][n])
__device__ uint32_t g_W1h[(NF / 2) * NH];
__device__ uint32_t g_W2h[(NH / 2) * NC];

// ---------------------------------------------------------------------------
__device__ __forceinline__ void mma_f16(float c[4], const uint32_t a[4], const uint32_t b[2]) {
    asm volatile(
        "mma.sync.aligned.m16n8k16.row.col.f32.f16.f16.f32 "
        "{%0,%1,%2,%3}, {%4,%5,%6,%7}, {%8,%9}, {%0,%1,%2,%3};"
        : "+f"(c[0]), "+f"(c[1]), "+f"(c[2]), "+f"(c[3])
        : "r"(a[0]), "r"(a[1]), "r"(a[2]), "r"(a[3]), "r"(b[0]), "r"(b[1]));
}

__device__ __forceinline__ void stcs_u4(uint4* p, uint4 v) {
    asm volatile("st.global.cs.v4.u32 [%0], {%1,%2,%3,%4};"
                 :: "l"(p), "r"(v.x), "r"(v.y), "r"(v.z), "r"(v.w) : "memory");
}

// ---------------------------------------------------------------------------
// Weight pre-conversion: fp32 [K][N] -> interleaved fp16 half2 [K/2][N].
__global__ void k_convW(const float* __restrict__ W1, const float* __restrict__ W2) {
    int i = blockIdx.x * blockDim.x + threadIdx.x;
    if (i < (NF / 2) * NH) {
        int k2 = i / NH, n = i % NH;
        __half2 h = __floats2half2_rn(W1[(2 * k2) * NH + n], W1[(2 * k2 + 1) * NH + n]);
        g_W1h[i] = *(const uint32_t*)&h;
    }
    if (i < (NH / 2) * NC) {
        int k2 = i / NC, n = i % NC;
        __half2 h = __floats2half2_rn(W2[(2 * k2) * NC + n], W2[(2 * k2 + 1) * NC + n]);
        g_W2h[i] = *(const uint32_t*)&h;
    }
}

// ---------------------------------------------------------------------------
// CSR build
__global__ void k_zero_csr() {
    int i = blockIdx.x * blockDim.x + threadIdx.x;
    if (i <= NNODE) g_rowptr[i] = 0;
    if (i < NNODE) g_cursor[i] = 0;
}

__global__ void k_hist(const int* __restrict__ rows, int E) {
    int e = blockIdx.x * blockDim.x + threadIdx.x;
    if (e < E) atomicAdd(&g_rowptr[rows[e] + 1], 1);
}

// inclusive block scan: 1024 elements per block (256 threads x 4)
__global__ void k_scan_block(int* __restrict__ d, int L, int* __restrict__ bsums) {
    __shared__ int warpsum[8];
    const int t = threadIdx.x, lane = t & 31, wid = t >> 5;
    const int base = blockIdx.x * 1024 + t * 4;
    int v0 = 0, v1 = 0, v2 = 0, v3 = 0;
    if (base + 3 < L) {
        int4 x = *(const int4*)(d + base);
        v0 = x.x; v1 = x.y; v2 = x.z; v3 = x.w;
    } else {
        if (base < L) v0 = d[base];
        if (base + 1 < L) v1 = d[base + 1];
        if (base + 2 < L) v2 = d[base + 2];
    }
    v1 += v0; v2 += v1; v3 += v2;
    int inc = v3;
#pragma unroll
    for (int o = 1; o < 32; o <<= 1) {
        int n = __shfl_up_sync(0xffffffffu, inc, o);
        if (lane >= o) inc += n;
    }
    if (lane == 31) warpsum[wid] = inc;
    __syncthreads();
    if (wid == 0) {
        int s = (lane < 8) ? warpsum[lane] : 0;
#pragma unroll
        for (int o = 1; o < 8; o <<= 1) {
            int n = __shfl_up_sync(0xffffffffu, s, o);
            if (lane >= o) s += n;
        }
        if (lane < 8) warpsum[lane] = s;
    }
    __syncthreads();
    int off = inc - v3;
    if (wid > 0) off += warpsum[wid - 1];
    v0 += off; v1 += off; v2 += off; v3 += off;
    if (base + 3 < L) {
        *(int4*)(d + base) = make_int4(v0, v1, v2, v3);
    } else {
        if (base < L) d[base] = v0;
        if (base + 1 < L) d[base + 1] = v1;
        if (base + 2 < L) d[base + 2] = v2;
    }
    if (t == 255) bsums[blockIdx.x] = v3;
}

__global__ void k_scan_sums(int* __restrict__ bsums, int nb) {
    __shared__ int ws[4];
    const int t = threadIdx.x, lane = t & 31, wid = t >> 5;
    int v = (t < nb) ? bsums[t] : 0;
    int inc = v;
#pragma unroll
    for (int o = 1; o < 32; o <<= 1) {
        int n = __shfl_up_sync(0xffffffffu, inc, o);
        if (lane >= o) inc += n;
    }
    if (lane == 31) ws[wid] = inc;
    __syncthreads();
    if (t == 0) {
        int run = 0;
#pragma unroll
        for (int i = 0; i < 4; i++) { int tmp = ws[i]; ws[i] = run; run += tmp; }
    }
    __syncthreads();
    int excl = inc - v + ws[wid];
    if (t < nb) bsums[t] = excl;
}

__global__ void k_scan_add(int* __restrict__ d, int L) {
    const int b = blockIdx.x;
    if (b == 0) return;
    const int add = g_bsums[b];
    const int base = b * 1024 + threadIdx.x * 4;
#pragma unroll
    for (int j = 0; j < 4; j++)
        if (base + j < L) d[base + j] += add;
}

__global__ void k_scatter(const int* __restrict__ rows, const int* __restrict__ cols,
                          const float* __restrict__ vals, int E) {
    int e = blockIdx.x * blockDim.x + threadIdx.x;
    if (e >= E) return;
    int r = rows[e];
    int idx = g_rowptr[r] + atomicAdd(&g_cursor[r], 1);
    g_edges[idx] = make_int2(cols[e], __float_as_int(vals[e]));
}

// ---------------------------------------------------------------------------
// FP16 GEMM (m16n8k16, fp32 accum), BM=128 x BN=256 x BK=32, 512 threads.
// A fp32 [M,512] read ONCE; B pre-converted fp16 (interleaved). Register
// double-buffered.
__global__ __launch_bounds__(512) void f16_gemm1(
        const float* __restrict__ A, __half* __restrict__ C, int M, int N, int K) {
    constexpr int BM = 128;
    constexpr int BN = 256;
    constexpr int BK = 32;
    constexpr int WM = 32;
    constexpr int WN = 64;
    constexpr int MFR = 2;
    constexpr int NFR = 8;
    constexpr int AS2 = 20;
    constexpr int BS2 = BN + 8;

    __shared__ __align__(16) __half2 As[BM][AS2];
    __shared__ __align__(16) __half2 Bs[BK / 2][BS2];

    const int tid  = threadIdx.x;
    const int warp = tid >> 5;
    const int lane = tid & 31;
    const int wm = (warp & 3) * WM;
    const int wn = (warp >> 2) * WN;
    const int rowBase = blockIdx.y * BM;

    float acc[MFR][NFR][4];
#pragma unroll
    for (int i = 0; i < MFR; i++)
#pragma unroll
        for (int j = 0; j < NFR; j++)
#pragma unroll
            for (int q = 0; q < 4; q++) acc[i][j][q] = 0.f;

    const int arow = tid >> 2;
    const int acol0 = (tid & 3) * 8;
    // B tile map: 16 k2-rows x 256 half2; 32 threads/row, 2 uint4 each
    const int brow2 = tid >> 5;          // 0..15
    const int bn4   = tid & 31;          // uint4 index base
    const int gr = rowBase + arow;
    const bool aok = (gr < M);
    const float* aBase = A + (size_t)gr * K + acol0;
    const uint32_t* bBase = g_W1h + (size_t)brow2 * N;

    // --- prologue: prefetch k0 = 0 ---
    float4 pa0 = make_float4(0.f, 0.f, 0.f, 0.f);
    float4 pa1 = make_float4(0.f, 0.f, 0.f, 0.f);
    uint4 pb[2];
    if (aok) { pa0 = *(const float4*)aBase; pa1 = *(const float4*)(aBase + 4); }
#pragma unroll
    for (int i = 0; i < 2; i++)
        pb[i] = *(const uint4*)(bBase + (bn4 + 32 * i) * 4);

    for (int k0 = 0; k0 < K; k0 += BK) {
        // --- store prefetched tile to smem (A: f32->f16 cvt; B: raw copy) ---
        {
            __half2 h[4];
            h[0] = __floats2half2_rn(pa0.x, pa0.y);
            h[1] = __floats2half2_rn(pa0.z, pa0.w);
            h[2] = __floats2half2_rn(pa1.x, pa1.y);
            h[3] = __floats2half2_rn(pa1.z, pa1.w);
            *(uint4*)&As[arow][acol0 / 2] = *(const uint4*)h;
        }
#pragma unroll
        for (int i = 0; i < 2; i++)
            *(uint4*)&Bs[brow2][(bn4 + 32 * i) * 4] = pb[i];
        __syncthreads();

        // --- prefetch next tile (overlaps the MMA phase below) ---
        const int kn = k0 + BK;
        if (kn < K) {
            if (aok) {
                pa0 = *(const float4*)(aBase + kn);
                pa1 = *(const float4*)(aBase + kn + 4);
            }
            const uint32_t* bp = bBase + (size_t)(kn / 2) * N;
#pragma unroll
            for (int i = 0; i < 2; i++)
                pb[i] = *(const uint4*)(bp + (bn4 + 32 * i) * 4);
        }

        // --- MMA phase ---
#pragma unroll
        for (int ks = 0; ks < BK / 16; ks++) {
            uint32_t afr[MFR][4];
            uint32_t bfr[NFR][2];
            const int ar = wm + (lane >> 2);
            const int kb = ks * 8 + (lane & 3);
#pragma unroll
            for (int mi = 0; mi < MFR; mi++) {
                afr[mi][0] = *(const uint32_t*)&As[ar + mi * 16 + 0][kb + 0];
                afr[mi][1] = *(const uint32_t*)&As[ar + mi * 16 + 8][kb + 0];
                afr[mi][2] = *(const uint32_t*)&As[ar + mi * 16 + 0][kb + 4];
                afr[mi][3] = *(const uint32_t*)&As[ar + mi * 16 + 8][kb + 4];
            }
            const int bc = wn + (lane >> 2);
#pragma unroll
            for (int ni = 0; ni < NFR; ni++) {
                bfr[ni][0] = *(const uint32_t*)&Bs[kb + 0][bc + ni * 8];
                bfr[ni][1] = *(const uint32_t*)&Bs[kb + 4][bc + ni * 8];
            }
#pragma unroll
            for (int mi = 0; mi < MFR; mi++)
#pragma unroll
                for (int ni = 0; ni < NFR; ni++)
                    mma_f16(acc[mi][ni], afr[mi], bfr[ni]);
        }
        __syncthreads();
    }

#pragma unroll
    for (int mi = 0; mi < MFR; mi++) {
#pragma unroll
        for (int ni = 0; ni < NFR; ni++) {
            const int r0 = rowBase + wm + mi * 16 + (lane >> 2);
            const int c0 = wn + ni * 8 + 2 * (lane & 3);
            if (r0 < M)
                *(__half2*)(C + (size_t)r0 * N + c0) =
                    __floats2half2_rn(acc[mi][ni][0], acc[mi][ni][1]);
            if (r0 + 8 < M)
                *(__half2*)(C + (size_t)(r0 + 8) * N + c0) =
                    __floats2half2_rn(acc[mi][ni][2], acc[mi][ni][3]);
        }
    }
}

// FP16 GEMM, fp16 A (direct copy), B pre-converted fp16; BM=128, BN=64,
// BK=32, 256 threads, warps 4x2. Register double-buffered. (GEMM2)
__global__ __launch_bounds__(256) void f16_gemm2(
        const __half* __restrict__ A, __half* __restrict__ C, int M, int N, int K) {
    constexpr int BM = 128;
    constexpr int BN = 64;
    constexpr int BK = 32;
    constexpr int WM = 32;   // 4 warps in M
    constexpr int WN = 32;   // 2 warps in N
    constexpr int MFR = 2;
    constexpr int NFR = 4;
    constexpr int AS2 = 20;
    constexpr int BS2 = BN + 8;

    __shared__ __align__(16) __half2 As[BM][AS2];
    __shared__ __align__(16) __half2 Bs[BK / 2][BS2];

    const int tid  = threadIdx.x;
    const int warp = tid >> 5;
    const int lane = tid & 31;
    const int wm = (warp % 4) * WM;
    const int wn = (warp / 4) * WN;
    const int rowBase = blockIdx.y * BM;

    float acc[MFR][NFR][4];
#pragma unroll
    for (int i = 0; i < MFR; i++)
#pragma unroll
        for (int j = 0; j < NFR; j++)
#pragma unroll
            for (int q = 0; q < 4; q++) acc[i][j][q] = 0.f;

    const int arow = tid >> 1;
    const int acolh = (tid & 1) * 16;
    // B tile map: 16 k2-rows x 64 half2; 16 threads/row, 1 uint4 each
    const int brow2 = tid >> 4;          // 0..15
    const int bn4   = tid & 15;
    const int gr = rowBase + arow;
    const bool aok = (gr < M);
    const __half* aBase = A + (size_t)gr * K + acolh;
    const uint32_t* bBase = g_W2h + (size_t)brow2 * N;

    // --- prologue: prefetch k0 = 0 ---
    uint4 pq0 = make_uint4(0, 0, 0, 0), pq1 = make_uint4(0, 0, 0, 0);
    uint4 pb;
    if (aok) {
        pq0 = *(const uint4*)aBase;
        pq1 = *(const uint4*)(aBase + 8);
    }
    pb = *(const uint4*)(bBase + bn4 * 4);

    for (int k0 = 0; k0 < K; k0 += BK) {
        *(uint4*)&As[arow][acolh / 2 + 0] = pq0;
        *(uint4*)&As[arow][acolh / 2 + 4] = pq1;
        *(uint4*)&Bs[brow2][bn4 * 4] = pb;
        __syncthreads();

        const int kn = k0 + BK;
        if (kn < K) {
            if (aok) {
                pq0 = *(const uint4*)(aBase + kn);
                pq1 = *(const uint4*)(aBase + kn + 8);
            }
            pb = *(const uint4*)(bBase + (size_t)(kn / 2) * N + bn4 * 4);
        }

#pragma unroll
        for (int ks = 0; ks < BK / 16; ks++) {
            uint32_t afr[MFR][4];
            uint32_t bfr[NFR][2];
            const int ar = wm + (lane >> 2);
            const int kb = ks * 8 + (lane & 3);
#pragma unroll
            for (int mi = 0; mi < MFR; mi++) {
                afr[mi][0] = *(const uint32_t*)&As[ar + mi * 16 + 0][kb + 0];
                afr[mi][1] = *(const uint32_t*)&As[ar + mi * 16 + 8][kb + 0];
                afr[mi][2] = *(const uint32_t*)&As[ar + mi * 16 + 0][kb + 4];
                afr[mi][3] = *(const uint32_t*)&As[ar + mi * 16 + 8][kb + 4];
            }
            const int bc = wn + (lane >> 2);
#pragma unroll
            for (int ni = 0; ni < NFR; ni++) {
                bfr[ni][0] = *(const uint32_t*)&Bs[kb + 0][bc + ni * 8];
                bfr[ni][1] = *(const uint32_t*)&Bs[kb + 4][bc + ni * 8];
            }
#pragma unroll
            for (int mi = 0; mi < MFR; mi++)
#pragma unroll
                for (int ni = 0; ni < NFR; ni++)
                    mma_f16(acc[mi][ni], afr[mi], bfr[ni]);
        }
        __syncthreads();
    }

#pragma unroll
    for (int mi = 0; mi < MFR; mi++) {
#pragma unroll
        for (int ni = 0; ni < NFR; ni++) {
            const int r0 = rowBase + wm + mi * 16 + (lane >> 2);
            const int c0 = wn + ni * 8 + 2 * (lane & 3);
            if (r0 < M)
                *(__half2*)(C + (size_t)r0 * N + c0) =
                    __floats2half2_rn(acc[mi][ni][0], acc[mi][ni][1]);
            if (r0 + 8 < M)
                *(__half2*)(C + (size_t)(r0 + 8) * N + c0) =
                    __floats2half2_rn(acc[mi][ni][2], acc[mi][ni][3]);
        }
    }
}

// ---------------------------------------------------------------------------
// CSR SpMM, F=256, fp16 source (R12 form). One warp per row; lane owns 8 halfs.
__global__ void spmm_csr_f256h(const __half* __restrict__ X, const float* __restrict__ bias,
                               __half* __restrict__ Y) {
    const int r = (blockIdx.x * blockDim.x + threadIdx.x) >> 5;
    const int lane = threadIdx.x & 31;
    if (r >= NNODE) return;
    const int start = g_rowptr[r];
    const int end   = g_rowptr[r + 1];
    float acc[8];
#pragma unroll
    for (int i = 0; i < 8; i++) acc[i] = 0.f;
    const uint4* Xb = (const uint4*)X + lane;
    for (int base = start; base < end; base += 32) {
        const int m = min(32, end - base);
        int2 ev = make_int2(0, 0);
        if (lane < m) ev = g_edges[base + lane];
#pragma unroll 4
        for (int j = 0; j < m; j++) {
            const int   cj = __shfl_sync(0xffffffffu, ev.x, j);
            const float vj = __int_as_float(__shfl_sync(0xffffffffu, ev.y, j));
            uint4 q = __ldg(Xb + (size_t)cj * 32);
            const __half2* hp = (const __half2*)&q;
#pragma unroll
            for (int i = 0; i < 4; i++) {
                float2 f = __half22float2(hp[i]);
                acc[i * 2 + 0] = fmaf(vj, f.x, acc[i * 2 + 0]);
                acc[i * 2 + 1] = fmaf(vj, f.y, acc[i * 2 + 1]);
            }
        }
    }
    float4 b0 = __ldg((const float4*)bias + lane * 2);
    float4 b1 = __ldg((const float4*)bias + lane * 2 + 1);
    float bb[8] = {b0.x, b0.y, b0.z, b0.w, b1.x, b1.y, b1.z, b1.w};
    __half2 o[4];
#pragma unroll
    for (int i = 0; i < 4; i++)
        o[i] = __floats2half2_rn(fmaxf(acc[i * 2] + bb[i * 2], 0.f),
                                 fmaxf(acc[i * 2 + 1] + bb[i * 2 + 1], 0.f));
    uint4 ov = *(const uint4*)o;
    stcs_u4((uint4*)Y + (size_t)r * 32 + lane, ov);
}

// CSR SpMM F=64 (fp16 source) fused with bias + log_softmax (R12 form).
__global__ void spmm_csr_f64h_ls(const __half* __restrict__ X, const float* __restrict__ bias,
                                 float* __restrict__ out) {
    const int r = (blockIdx.x * blockDim.x + threadIdx.x) >> 5;
    const int lane = threadIdx.x & 31;
    if (r >= NNODE) return;
    const int start = g_rowptr[r];
    const int end   = g_rowptr[r + 1];
    float2 acc = make_float2(0.f, 0.f);
    const uint32_t* Xb = (const uint32_t*)X + lane;
    for (int base = start; base < end; base += 32) {
        const int m = min(32, end - base);
        int2 ev = make_int2(0, 0);
        if (lane < m) ev = g_edges[base + lane];
#pragma unroll 4
        for (int j = 0; j < m; j++) {
            const int   cj = __shfl_sync(0xffffffffu, ev.x, j);
            const float vj = __int_as_float(__shfl_sync(0xffffffffu, ev.y, j));
            uint32_t q = __ldg(Xb + (size_t)cj * 32);
            float2 xs = __half22float2(*(const __half2*)&q);
            acc.x = fmaf(vj, xs.x, acc.x);
            acc.y = fmaf(vj, xs.y, acc.y);
        }
    }
    float2 bb = __ldg((const float2*)bias + lane);
    float v0 = acc.x + bb.x;
    float v1 = acc.y + bb.y;
    float mx = fmaxf(v0, v1);
#pragma unroll
    for (int o = 16; o; o >>= 1) mx = fmaxf(mx, __shfl_xor_sync(0xffffffffu, mx, o));
    float s = __expf(v0 - mx) + __expf(v1 - mx);
#pragma unroll
    for (int o = 16; o; o >>= 1) s += __shfl_xor_sync(0xffffffffu, s, o);
    float lse = mx + __logf(s);
    *(float2*)(out + (size_t)r * 64 + lane * 2) = make_float2(v0 - lse, v1 - lse);
}

// ---------------------------------------------------------------------------
extern "C" void kernel_launch(void* const* d_in, const int* in_sizes, int n_in,
                              void* d_out, int out_size) {
    const float* x    = (const float*)d_in[0];
    const int*   erow = (const int*)d_in[1];
    const int*   ecol = (const int*)d_in[2];
    const float* eval_ = (const float*)d_in[3];
    const float* W1   = (const float*)d_in[4];
    const float* b1   = (const float*)d_in[5];
    const float* W2   = (const float*)d_in[6];
    const float* b2   = (const float*)d_in[7];
    float* out = (float*)d_out;

    const int E = in_sizes[1];
    const int M = in_sizes[0] / NF;  // 100000

    __half *xw1, *h, *hw2;
    int *rowptr, *bsums;
    cudaGetSymbolAddress((void**)&xw1, g_xw1);
    cudaGetSymbolAddress((void**)&h, g_h);
    cudaGetSymbolAddress((void**)&hw2, g_hw2);
    cudaGetSymbolAddress((void**)&rowptr, g_rowptr);
    cudaGetSymbolAddress((void**)&bsums, g_bsums);

    const int L = NNODE + 1;
    const int nscan = (L + 1023) / 1024;  // 98

    // One-time side resources (host-side only; no device memory involved).
    static cudaStream_t s2 = nullptr;
    static cudaEvent_t evFork = nullptr, evJoin = nullptr;
    if (!s2) {
        cudaStreamCreateWithFlags(&s2, cudaStreamNonBlocking);
        cudaEventCreateWithFlags(&evFork, cudaEventDisableTiming);
        cudaEventCreateWithFlags(&evJoin, cudaEventDisableTiming);
    }

    // Fork: CSR build on s2, concurrent with weight conversion + GEMM1.
    cudaEventRecord(evFork, 0);
    cudaStreamWaitEvent(s2, evFork, 0);

    // --- CSR build (stream s2) ---
    k_zero_csr<<<(NNODE + 256) / 256, 256, 0, s2>>>();
    k_hist<<<(E + 255) / 256, 256, 0, s2>>>(erow, E);
    k_scan_block<<<nscan, 256, 0, s2>>>(rowptr, L, bsums);
    k_scan_sums<<<1, 128, 0, s2>>>(bsums, nscan);
    k_scan_add<<<nscan, 256, 0, s2>>>(rowptr, L);
    k_scatter<<<(E + 255) / 256, 256, 0, s2>>>(erow, ecol, eval_, E);
    cudaEventRecord(evJoin, s2);

    // --- weight conversion + layer 1 GEMM (main stream) ---
    k_convW<<<((NF / 2) * NH + 255) / 256, 256>>>(W1, W2);
    f16_gemm1<<<dim3(1, (M + 127) / 128), 512>>>(x, xw1, M, NH, NF);

    // Join: spmm1 needs both GEMM1 and the CSR structures.
    cudaStreamWaitEvent(0, evJoin, 0);

    // spmm1 (CSR gather, fp16 source L2-resident) + fused bias/relu
    {
        int blocks = (NNODE * 32 + 255) / 256;
        spmm_csr_f256h<<<blocks, 256>>>(xw1, b1, h);
    }

    // layer 2: HW2 = h @ W2  (fp16 tensor cores, pre-converted B)
    f16_gemm2<<<dim3(1, (M + 127) / 128), 256>>>(h, hw2, M, NC, NH);

    // spmm2 (CSR gather, fp16 source) + fused bias + log_softmax
    {
        int blocks = (NNODE * 32 + 255) / 256;
        spmm_csr_f64h_ls<<<blocks, 256>>>(hw2, b2, out);
    }
}

// round 16
// speedup vs baseline: 1.0685x; 1.0061x over previous
#include <cuda_runtime.h>
#include <cuda_fp16.h>
#include <cstdint>

// Problem constants (shapes fixed by the reference)
constexpr int NF = 512;   // input features
constexpr int NH = 256;   // hidden
constexpr int NC = 64;    // classes
constexpr int NNODE = 100000;
constexpr int EMAX = 3200000;

// Scratch (allocation-free rule: __device__ globals)
__device__ __half   g_xw1[(size_t)NNODE * NH];  // x @ W1 (fp16)
__device__ __half   g_h[(size_t)NNODE * NH];    // spmm1 out / h (fp16)
__device__ __half   g_hw2[(size_t)NNODE * NC];  // h @ W2 (fp16)
__device__ int      g_rowptr[NNODE + 1];        // block-local inclusive scans
__device__ int      g_cursor[NNODE];
__device__ int2     g_edges[EMAX];              // (col, val-bits) sorted by row
__device__ int      g_bsums[128];               // exclusive block offsets
// Pre-converted weights, k-pair interleaved: [k2][n] = half2(W[2k2][n], W[2k2+1][n])
__device__ uint32_t g_W1h[(NF / 2) * NH];
__device__ uint32_t g_W2h[(NH / 2) * NC];

// ---------------------------------------------------------------------------
__device__ __forceinline__ void mma_f16(float c[4], const uint32_t a[4], const uint32_t b[2]) {
    asm volatile(
        "mma.sync.aligned.m16n8k16.row.col.f32.f16.f16.f32 "
        "{%0,%1,%2,%3}, {%4,%5,%6,%7}, {%8,%9}, {%0,%1,%2,%3};"
        : "+f"(c[0]), "+f"(c[1]), "+f"(c[2]), "+f"(c[3])
        : "r"(a[0]), "r"(a[1]), "r"(a[2]), "r"(a[3]), "r"(b[0]), "r"(b[1]));
}

__device__ __forceinline__ void stcs_u4(uint4* p, uint4 v) {
    asm volatile("st.global.cs.v4.u32 [%0], {%1,%2,%3,%4};"
                 :: "l"(p), "r"(v.x), "r"(v.y), "r"(v.z), "r"(v.w) : "memory");
}

// row start/end in g_edges, folding in the block-offset term
__device__ __forceinline__ int row_off(int i) {
    return g_rowptr[i] + g_bsums[i >> 10];
}

// ---------------------------------------------------------------------------
// Weight pre-conversion: fp32 [K][N] -> interleaved fp16 half2 [K/2][N].
__global__ void k_convW(const float* __restrict__ W1, const float* __restrict__ W2) {
    int i = blockIdx.x * blockDim.x + threadIdx.x;
    if (i < (NF / 2) * NH) {
        int k2 = i / NH, n = i % NH;
        __half2 h = __floats2half2_rn(W1[(2 * k2) * NH + n], W1[(2 * k2 + 1) * NH + n]);
        g_W1h[i] = *(const uint32_t*)&h;
    }
    if (i < (NH / 2) * NC) {
        int k2 = i / NC, n = i % NC;
        __half2 h = __floats2half2_rn(W2[(2 * k2) * NC + n], W2[(2 * k2 + 1) * NC + n]);
        g_W2h[i] = *(const uint32_t*)&h;
    }
}

// ---------------------------------------------------------------------------
// CSR build
__global__ void k_zero_csr() {
    int i = blockIdx.x * blockDim.x + threadIdx.x;
    if (i <= NNODE) g_rowptr[i] = 0;
    if (i < NNODE) g_cursor[i] = 0;
}

// histogram, 4 edges per thread (int4 loads)
__global__ void k_hist4(const int* __restrict__ rows, int E) {
    int i = (blockIdx.x * blockDim.x + threadIdx.x) * 4;
    if (i + 3 < E) {
        int4 r = *(const int4*)(rows + i);
        atomicAdd(&g_rowptr[r.x + 1], 1);
        atomicAdd(&g_rowptr[r.y + 1], 1);
        atomicAdd(&g_rowptr[r.z + 1], 1);
        atomicAdd(&g_rowptr[r.w + 1], 1);
    } else {
        for (int j = i; j < E; j++) atomicAdd(&g_rowptr[rows[j] + 1], 1);
    }
}

// inclusive block scan: 1024 elements per block (256 threads x 4).
// Leaves rowptr as BLOCK-LOCAL inclusive scans; block offsets go to bsums.
__global__ void k_scan_block(int* __restrict__ d, int L, int* __restrict__ bsums) {
    __shared__ int warpsum[8];
    const int t = threadIdx.x, lane = t & 31, wid = t >> 5;
    const int base = blockIdx.x * 1024 + t * 4;
    int v0 = 0, v1 = 0, v2 = 0, v3 = 0;
    if (base + 3 < L) {
        int4 x = *(const int4*)(d + base);
        v0 = x.x; v1 = x.y; v2 = x.z; v3 = x.w;
    } else {
        if (base < L) v0 = d[base];
        if (base + 1 < L) v1 = d[base + 1];
        if (base + 2 < L) v2 = d[base + 2];
    }
    v1 += v0; v2 += v1; v3 += v2;
    int inc = v3;
#pragma unroll
    for (int o = 1; o < 32; o <<= 1) {
        int n = __shfl_up_sync(0xffffffffu, inc, o);
        if (lane >= o) inc += n;
    }
    if (lane == 31) warpsum[wid] = inc;
    __syncthreads();
    if (wid == 0) {
        int s = (lane < 8) ? warpsum[lane] : 0;
#pragma unroll
        for (int o = 1; o < 8; o <<= 1) {
            int n = __shfl_up_sync(0xffffffffu, s, o);
            if (lane >= o) s += n;
        }
        if (lane < 8) warpsum[lane] = s;
    }
    __syncthreads();
    int off = inc - v3;
    if (wid > 0) off += warpsum[wid - 1];
    v0 += off; v1 += off; v2 += off; v3 += off;
    if (base + 3 < L) {
        *(int4*)(d + base) = make_int4(v0, v1, v2, v3);
    } else {
        if (base < L) d[base] = v0;
        if (base + 1 < L) d[base + 1] = v1;
        if (base + 2 < L) d[base + 2] = v2;
    }
    if (t == 255) bsums[blockIdx.x] = v3;
}

__global__ void k_scan_sums(int* __restrict__ bsums, int nb) {
    __shared__ int ws[4];
    const int t = threadIdx.x, lane = t & 31, wid = t >> 5;
    int v = (t < nb) ? bsums[t] : 0;
    int inc = v;
#pragma unroll
    for (int o = 1; o < 32; o <<= 1) {
        int n = __shfl_up_sync(0xffffffffu, inc, o);
        if (lane >= o) inc += n;
    }
    if (lane == 31) ws[wid] = inc;
    __syncthreads();
    if (t == 0) {
        int run = 0;
#pragma unroll
        for (int i = 0; i < 4; i++) { int tmp = ws[i]; ws[i] = run; run += tmp; }
    }
    __syncthreads();
    int excl = inc - v + ws[wid];
    if (t < nb) bsums[t] = excl;
}

__global__ void k_scatter(const int* __restrict__ rows, const int* __restrict__ cols,
                          const float* __restrict__ vals, int E) {
    int e = blockIdx.x * blockDim.x + threadIdx.x;
    if (e >= E) return;
    int r = rows[e];
    int idx = row_off(r) + atomicAdd(&g_cursor[r], 1);
    g_edges[idx] = make_int2(cols[e], __float_as_int(vals[e]));
}

// ---------------------------------------------------------------------------
// FP16 GEMM (m16n8k16, fp32 accum), BM=128 x BN=256 x BK=32, 512 threads.
// A fp32 [M,512] read ONCE; B pre-converted fp16 (interleaved). Register
// double-buffered.
__global__ __launch_bounds__(512) void f16_gemm1(
        const float* __restrict__ A, __half* __restrict__ C, int M, int N, int K) {
    constexpr int BM = 128;
    constexpr int BN = 256;
    constexpr int BK = 32;
    constexpr int WM = 32;
    constexpr int WN = 64;
    constexpr int MFR = 2;
    constexpr int NFR = 8;
    constexpr int AS2 = 20;
    constexpr int BS2 = BN + 8;

    __shared__ __align__(16) __half2 As[BM][AS2];
    __shared__ __align__(16) __half2 Bs[BK / 2][BS2];

    const int tid  = threadIdx.x;
    const int warp = tid >> 5;
    const int lane = tid & 31;
    const int wm = (warp & 3) * WM;
    const int wn = (warp >> 2) * WN;
    const int rowBase = blockIdx.y * BM;

    float acc[MFR][NFR][4];
#pragma unroll
    for (int i = 0; i < MFR; i++)
#pragma unroll
        for (int j = 0; j < NFR; j++)
#pragma unroll
            for (int q = 0; q < 4; q++) acc[i][j][q] = 0.f;

    const int arow = tid >> 2;
    const int acol0 = (tid & 3) * 8;
    const int brow2 = tid >> 5;          // 0..15
    const int bn4   = tid & 31;
    const int gr = rowBase + arow;
    const bool aok = (gr < M);
    const float* aBase = A + (size_t)gr * K + acol0;
    const uint32_t* bBase = g_W1h + (size_t)brow2 * N;

    float4 pa0 = make_float4(0.f, 0.f, 0.f, 0.f);
    float4 pa1 = make_float4(0.f, 0.f, 0.f, 0.f);
    uint4 pb[2];
    if (aok) { pa0 = *(const float4*)aBase; pa1 = *(const float4*)(aBase + 4); }
#pragma unroll
    for (int i = 0; i < 2; i++)
        pb[i] = *(const uint4*)(bBase + (bn4 + 32 * i) * 4);

    for (int k0 = 0; k0 < K; k0 += BK) {
        {
            __half2 h[4];
            h[0] = __floats2half2_rn(pa0.x, pa0.y);
            h[1] = __floats2half2_rn(pa0.z, pa0.w);
            h[2] = __floats2half2_rn(pa1.x, pa1.y);
            h[3] = __floats2half2_rn(pa1.z, pa1.w);
            *(uint4*)&As[arow][acol0 / 2] = *(const uint4*)h;
        }
#pragma unroll
        for (int i = 0; i < 2; i++)
            *(uint4*)&Bs[brow2][(bn4 + 32 * i) * 4] = pb[i];
        __syncthreads();

        const int kn = k0 + BK;
        if (kn < K) {
            if (aok) {
                pa0 = *(const float4*)(aBase + kn);
                pa1 = *(const float4*)(aBase + kn + 4);
            }
            const uint32_t* bp = bBase + (size_t)(kn / 2) * N;
#pragma unroll
            for (int i = 0; i < 2; i++)
                pb[i] = *(const uint4*)(bp + (bn4 + 32 * i) * 4);
        }

#pragma unroll
        for (int ks = 0; ks < BK / 16; ks++) {
            uint32_t afr[MFR][4];
            uint32_t bfr[NFR][2];
            const int ar = wm + (lane >> 2);
            const int kb = ks * 8 + (lane & 3);
#pragma unroll
            for (int mi = 0; mi < MFR; mi++) {
                afr[mi][0] = *(const uint32_t*)&As[ar + mi * 16 + 0][kb + 0];
                afr[mi][1] = *(const uint32_t*)&As[ar + mi * 16 + 8][kb + 0];
                afr[mi][2] = *(const uint32_t*)&As[ar + mi * 16 + 0][kb + 4];
                afr[mi][3] = *(const uint32_t*)&As[ar + mi * 16 + 8][kb + 4];
            }
            const int bc = wn + (lane >> 2);
#pragma unroll
            for (int ni = 0; ni < NFR; ni++) {
                bfr[ni][0] = *(const uint32_t*)&Bs[kb + 0][bc + ni * 8];
                bfr[ni][1] = *(const uint32_t*)&Bs[kb + 4][bc + ni * 8];
            }
#pragma unroll
            for (int mi = 0; mi < MFR; mi++)
#pragma unroll
                for (int ni = 0; ni < NFR; ni++)
                    mma_f16(acc[mi][ni], afr[mi], bfr[ni]);
        }
        __syncthreads();
    }

#pragma unroll
    for (int mi = 0; mi < MFR; mi++) {
#pragma unroll
        for (int ni = 0; ni < NFR; ni++) {
            const int r0 = rowBase + wm + mi * 16 + (lane >> 2);
            const int c0 = wn + ni * 8 + 2 * (lane & 3);
            if (r0 < M)
                *(__half2*)(C + (size_t)r0 * N + c0) =
                    __floats2half2_rn(acc[mi][ni][0], acc[mi][ni][1]);
            if (r0 + 8 < M)
                *(__half2*)(C + (size_t)(r0 + 8) * N + c0) =
                    __floats2half2_rn(acc[mi][ni][2], acc[mi][ni][3]);
        }
    }
}

// FP16 GEMM, fp16 A (direct copy), B pre-converted fp16; BM=128, BN=64,
// BK=32, 256 threads, warps 4x2. Register double-buffered. (GEMM2)
__global__ __launch_bounds__(256) void f16_gemm2(
        const __half* __restrict__ A, __half* __restrict__ C, int M, int N, int K) {
    constexpr int BM = 128;
    constexpr int BN = 64;
    constexpr int BK = 32;
    constexpr int WM = 32;
    constexpr int WN = 32;
    constexpr int MFR = 2;
    constexpr int NFR = 4;
    constexpr int AS2 = 20;
    constexpr int BS2 = BN + 8;

    __shared__ __align__(16) __half2 As[BM][AS2];
    __shared__ __align__(16) __half2 Bs[BK / 2][BS2];

    const int tid  = threadIdx.x;
    const int warp = tid >> 5;
    const int lane = tid & 31;
    const int wm = (warp % 4) * WM;
    const int wn = (warp / 4) * WN;
    const int rowBase = blockIdx.y * BM;

    float acc[MFR][NFR][4];
#pragma unroll
    for (int i = 0; i < MFR; i++)
#pragma unroll
        for (int j = 0; j < NFR; j++)
#pragma unroll
            for (int q = 0; q < 4; q++) acc[i][j][q] = 0.f;

    const int arow = tid >> 1;
    const int acolh = (tid & 1) * 16;
    const int brow2 = tid >> 4;
    const int bn4   = tid & 15;
    const int gr = rowBase + arow;
    const bool aok = (gr < M);
    const __half* aBase = A + (size_t)gr * K + acolh;
    const uint32_t* bBase = g_W2h + (size_t)brow2 * N;

    uint4 pq0 = make_uint4(0, 0, 0, 0), pq1 = make_uint4(0, 0, 0, 0);
    uint4 pb;
    if (aok) {
        pq0 = *(const uint4*)aBase;
        pq1 = *(const uint4*)(aBase + 8);
    }
    pb = *(const uint4*)(bBase + bn4 * 4);

    for (int k0 = 0; k0 < K; k0 += BK) {
        *(uint4*)&As[arow][acolh / 2 + 0] = pq0;
        *(uint4*)&As[arow][acolh / 2 + 4] = pq1;
        *(uint4*)&Bs[brow2][bn4 * 4] = pb;
        __syncthreads();

        const int kn = k0 + BK;
        if (kn < K) {
            if (aok) {
                pq0 = *(const uint4*)(aBase + kn);
                pq1 = *(const uint4*)(aBase + kn + 8);
            }
            pb = *(const uint4*)(bBase + (size_t)(kn / 2) * N + bn4 * 4);
        }

#pragma unroll
        for (int ks = 0; ks < BK / 16; ks++) {
            uint32_t afr[MFR][4];
            uint32_t bfr[NFR][2];
            const int ar = wm + (lane >> 2);
            const int kb = ks * 8 + (lane & 3);
#pragma unroll
            for (int mi = 0; mi < MFR; mi++) {
                afr[mi][0] = *(const uint32_t*)&As[ar + mi * 16 + 0][kb + 0];
                afr[mi][1] = *(const uint32_t*)&As[ar + mi * 16 + 8][kb + 0];
                afr[mi][2] = *(const uint32_t*)&As[ar + mi * 16 + 0][kb + 4];
                afr[mi][3] = *(const uint32_t*)&As[ar + mi * 16 + 8][kb + 4];
            }
            const int bc = wn + (lane >> 2);
#pragma unroll
            for (int ni = 0; ni < NFR; ni++) {
                bfr[ni][0] = *(const uint32_t*)&Bs[kb + 0][bc + ni * 8];
                bfr[ni][1] = *(const uint32_t*)&Bs[kb + 4][bc + ni * 8];
            }
#pragma unroll
            for (int mi = 0; mi < MFR; mi++)
#pragma unroll
                for (int ni = 0; ni < NFR; ni++)
                    mma_f16(acc[mi][ni], afr[mi], bfr[ni]);
        }
        __syncthreads();
    }

#pragma unroll
    for (int mi = 0; mi < MFR; mi++) {
#pragma unroll
        for (int ni = 0; ni < NFR; ni++) {
            const int r0 = rowBase + wm + mi * 16 + (lane >> 2);
            const int c0 = wn + ni * 8 + 2 * (lane & 3);
            if (r0 < M)
                *(__half2*)(C + (size_t)r0 * N + c0) =
                    __floats2half2_rn(acc[mi][ni][0], acc[mi][ni][1]);
            if (r0 + 8 < M)
                *(__half2*)(C + (size_t)(r0 + 8) * N + c0) =
                    __floats2half2_rn(acc[mi][ni][2], acc[mi][ni][3]);
        }
    }
}

// ---------------------------------------------------------------------------
// CSR SpMM, F=256, fp16 source (R12 form). One warp per row; lane owns 8 halfs.
__global__ void spmm_csr_f256h(const __half* __restrict__ X, const float* __restrict__ bias,
                               __half* __restrict__ Y) {
    const int r = (blockIdx.x * blockDim.x + threadIdx.x) >> 5;
    const int lane = threadIdx.x & 31;
    if (r >= NNODE) return;
    const int start = row_off(r);
    const int end   = row_off(r + 1);
    float acc[8];
#pragma unroll
    for (int i = 0; i < 8; i++) acc[i] = 0.f;
    const uint4* Xb = (const uint4*)X + lane;
    for (int base = start; base < end; base += 32) {
        const int m = min(32, end - base);
        int2 ev = make_int2(0, 0);
        if (lane < m) ev = g_edges[base + lane];
#pragma unroll 4
        for (int j = 0; j < m; j++) {
            const int   cj = __shfl_sync(0xffffffffu, ev.x, j);
            const float vj = __int_as_float(__shfl_sync(0xffffffffu, ev.y, j));
            uint4 q = __ldg(Xb + (size_t)cj * 32);
            const __half2* hp = (const __half2*)&q;
#pragma unroll
            for (int i = 0; i < 4; i++) {
                float2 f = __half22float2(hp[i]);
                acc[i * 2 + 0] = fmaf(vj, f.x, acc[i * 2 + 0]);
                acc[i * 2 + 1] = fmaf(vj, f.y, acc[i * 2 + 1]);
            }
        }
    }
    float4 b0 = __ldg((const float4*)bias + lane * 2);
    float4 b1 = __ldg((const float4*)bias + lane * 2 + 1);
    float bb[8] = {b0.x, b0.y, b0.z, b0.w, b1.x, b1.y, b1.z, b1.w};
    __half2 o[4];
#pragma unroll
    for (int i = 0; i < 4; i++)
        o[i] = __floats2half2_rn(fmaxf(acc[i * 2] + bb[i * 2], 0.f),
                                 fmaxf(acc[i * 2 + 1] + bb[i * 2 + 1], 0.f));
    uint4 ov = *(const uint4*)o;
    stcs_u4((uint4*)Y + (size_t)r * 32 + lane, ov);
}

// CSR SpMM F=64 (fp16 source) fused with bias + log_softmax (R12 form).
__global__ void spmm_csr_f64h_ls(const __half* __restrict__ X, const float* __restrict__ bias,
                                 float* __restrict__ out) {
    const int r = (blockIdx.x * blockDim.x + threadIdx.x) >> 5;
    const int lane = threadIdx.x & 31;
    if (r >= NNODE) return;
    const int start = row_off(r);
    const int end   = row_off(r + 1);
    float2 acc = make_float2(0.f, 0.f);
    const uint32_t* Xb = (const uint32_t*)X + lane;
    for (int base = start; base < end; base += 32) {
        const int m = min(32, end - base);
        int2 ev = make_int2(0, 0);
        if (lane < m) ev = g_edges[base + lane];
#pragma unroll 4
        for (int j = 0; j < m; j++) {
            const int   cj = __shfl_sync(0xffffffffu, ev.x, j);
            const float vj = __int_as_float(__shfl_sync(0xffffffffu, ev.y, j));
            uint32_t q = __ldg(Xb + (size_t)cj * 32);
            float2 xs = __half22float2(*(const __half2*)&q);
            acc.x = fmaf(vj, xs.x, acc.x);
            acc.y = fmaf(vj, xs.y, acc.y);
        }
    }
    float2 bb = __ldg((const float2*)bias + lane);
    float v0 = acc.x + bb.x;
    float v1 = acc.y + bb.y;
    float mx = fmaxf(v0, v1);
#pragma unroll
    for (int o = 16; o; o >>= 1) mx = fmaxf(mx, __shfl_xor_sync(0xffffffffu, mx, o));
    float s = __expf(v0 - mx) + __expf(v1 - mx);
#pragma unroll
    for (int o = 16; o; o >>= 1) s += __shfl_xor_sync(0xffffffffu, s, o);
    float lse = mx + __logf(s);
    *(float2*)(out + (size_t)r * 64 + lane * 2) = make_float2(v0 - lse, v1 - lse);
}

// ---------------------------------------------------------------------------
extern "C" void kernel_launch(void* const* d_in, const int* in_sizes, int n_in,
                              void* d_out, int out_size) {
    const float* x    = (const float*)d_in[0];
    const int*   erow = (const int*)d_in[1];
    const int*   ecol = (const int*)d_in[2];
    const float* eval_ = (const float*)d_in[3];
    const float* W1   = (const float*)d_in[4];
    const float* b1   = (const float*)d_in[5];
    const float* W2   = (const float*)d_in[6];
    const float* b2   = (const float*)d_in[7];
    float* out = (float*)d_out;

    const int E = in_sizes[1];
    const int M = in_sizes[0] / NF;  // 100000

    __half *xw1, *h, *hw2;
    int *rowptr, *bsums;
    cudaGetSymbolAddress((void**)&xw1, g_xw1);
    cudaGetSymbolAddress((void**)&h, g_h);
    cudaGetSymbolAddress((void**)&hw2, g_hw2);
    cudaGetSymbolAddress((void**)&rowptr, g_rowptr);
    cudaGetSymbolAddress((void**)&bsums, g_bsums);

    const int L = NNODE + 1;
    const int nscan = (L + 1023) / 1024;  // 98

    // One-time side resources (host-side only; no device memory involved).
    static cudaStream_t s2 = nullptr;
    static cudaEvent_t evFork = nullptr, evJoin = nullptr;
    if (!s2) {
        cudaStreamCreateWithFlags(&s2, cudaStreamNonBlocking);
        cudaEventCreateWithFlags(&evFork, cudaEventDisableTiming);
        cudaEventCreateWithFlags(&evJoin, cudaEventDisableTiming);
    }

    // Fork: CSR build on s2, concurrent with weight conversion + GEMM1.
    cudaEventRecord(evFork, 0);
    cudaStreamWaitEvent(s2, evFork, 0);

    // Host launch order interleaves the two streams (execution order is set by
    // stream/event deps, not call order) so GEMM1 is the 4th launch for ncu.
    k_convW<<<((NF / 2) * NH + 255) / 256, 256>>>(W1, W2);            // 0 main
    k_zero_csr<<<(NNODE + 256) / 256, 256, 0, s2>>>();                // 1 s2
    k_hist4<<<(E / 4 + 255) / 256, 256, 0, s2>>>(erow, E);            // 2 s2
    f16_gemm1<<<dim3(1, (M + 127) / 128), 512>>>(x, xw1, M, NH, NF);  // 3 main
    k_scan_block<<<nscan, 256, 0, s2>>>(rowptr, L, bsums);            // 4 s2
    k_scan_sums<<<1, 128, 0, s2>>>(bsums, nscan);                     // 5 s2
    k_scatter<<<(E + 255) / 256, 256, 0, s2>>>(erow, ecol, eval_, E); // 6 s2
    cudaEventRecord(evJoin, s2);

    // Join: spmm1 needs both GEMM1 and the CSR structures.
    cudaStreamWaitEvent(0, evJoin, 0);

    // spmm1 (CSR gather, fp16 source L2-resident) + fused bias/relu
    {
        int blocks = (NNODE * 32 + 255) / 256;
        spmm_csr_f256h<<<blocks, 256>>>(xw1, b1, h);
    }

    // layer 2: HW2 = h @ W2  (fp16 tensor cores, pre-converted B)
    f16_gemm2<<<dim3(1, (M + 127) / 128), 256>>>(h, hw2, M, NC, NH);

    // spmm2 (CSR gather, fp16 source) + fused bias + log_softmax
    {
        int blocks = (NNODE * 32 + 255) / 256;
        spmm_csr_f64h_ls<<<blocks, 256>>>(hw2, b2, out);
    }
}

// round 17
// speedup vs baseline: 1.0838x; 1.0143x over previous
#include <cuda_runtime.h>
#include <cuda_fp16.h>
#include <cstdint>

// Problem constants (shapes fixed by the reference)
constexpr int NF = 512;   // input features
constexpr int NH = 256;   // hidden
constexpr int NC = 64;    // classes
constexpr int NNODE = 100000;
constexpr int EMAX = 3200000;

// Scratch (allocation-free rule: __device__ globals)
__device__ __half   g_xw1[(size_t)NNODE * NH];  // x @ W1 (fp16)
__device__ __half   g_h[(size_t)NNODE * NH];    // spmm1 out / h (fp16)
__device__ __half   g_hw2[(size_t)NNODE * NC];  // h @ W2 (fp16)
__device__ int      g_rowptr[NNODE + 1];        // block-local inclusive scans
__device__ int      g_cursor[NNODE];
__device__ int2     g_edges[EMAX];              // (col, val-bits) sorted by row
__device__ int      g_bsums[128];               // exclusive block offsets
// Pre-converted weights, k-pair interleaved: [k2][n] = half2(W[2k2][n], W[2k2+1][n])
__device__ uint32_t g_W1h[(NF / 2) * NH];
__device__ uint32_t g_W2h[(NH / 2) * NC];

// ---------------------------------------------------------------------------
__device__ __forceinline__ void mma_f16(float c[4], const uint32_t a[4], const uint32_t b[2]) {
    asm volatile(
        "mma.sync.aligned.m16n8k16.row.col.f32.f16.f16.f32 "
        "{%0,%1,%2,%3}, {%4,%5,%6,%7}, {%8,%9}, {%0,%1,%2,%3};"
        : "+f"(c[0]), "+f"(c[1]), "+f"(c[2]), "+f"(c[3])
        : "r"(a[0]), "r"(a[1]), "r"(a[2]), "r"(a[3]), "r"(b[0]), "r"(b[1]));
}

__device__ __forceinline__ void stcs_u4(uint4* p, uint4 v) {
    asm volatile("st.global.cs.v4.u32 [%0], {%1,%2,%3,%4};"
                 :: "l"(p), "r"(v.x), "r"(v.y), "r"(v.z), "r"(v.w) : "memory");
}

// row start/end in g_edges, folding in the block-offset term
__device__ __forceinline__ int row_off(int i) {
    return g_rowptr[i] + g_bsums[i >> 10];
}

// ---------------------------------------------------------------------------
// Weight pre-conversion: fp32 [K][N] -> interleaved fp16 half2 [K/2][N].
__global__ void k_convW(const float* __restrict__ W1, const float* __restrict__ W2) {
    int i = blockIdx.x * blockDim.x + threadIdx.x;
    if (i < (NF / 2) * NH) {
        int k2 = i / NH, n = i % NH;
        __half2 h = __floats2half2_rn(W1[(2 * k2) * NH + n], W1[(2 * k2 + 1) * NH + n]);
        g_W1h[i] = *(const uint32_t*)&h;
    }
    if (i < (NH / 2) * NC) {
        int k2 = i / NC, n = i % NC;
        __half2 h = __floats2half2_rn(W2[(2 * k2) * NC + n], W2[(2 * k2 + 1) * NC + n]);
        g_W2h[i] = *(const uint32_t*)&h;
    }
}

// ---------------------------------------------------------------------------
// CSR build
__global__ void k_zero_csr() {
    int i = blockIdx.x * blockDim.x + threadIdx.x;
    if (i <= NNODE) g_rowptr[i] = 0;
    if (i < NNODE) g_cursor[i] = 0;
}

// histogram, 4 edges per thread (int4 loads)
__global__ void k_hist4(const int* __restrict__ rows, int E) {
    int i = (blockIdx.x * blockDim.x + threadIdx.x) * 4;
    if (i + 3 < E) {
        int4 r = *(const int4*)(rows + i);
        atomicAdd(&g_rowptr[r.x + 1], 1);
        atomicAdd(&g_rowptr[r.y + 1], 1);
        atomicAdd(&g_rowptr[r.z + 1], 1);
        atomicAdd(&g_rowptr[r.w + 1], 1);
    } else {
        for (int j = i; j < E; j++) atomicAdd(&g_rowptr[rows[j] + 1], 1);
    }
}

// inclusive block scan: 1024 elements per block (256 threads x 4).
// Leaves rowptr as BLOCK-LOCAL inclusive scans; block offsets go to bsums.
__global__ void k_scan_block(int* __restrict__ d, int L, int* __restrict__ bsums) {
    __shared__ int warpsum[8];
    const int t = threadIdx.x, lane = t & 31, wid = t >> 5;
    const int base = blockIdx.x * 1024 + t * 4;
    int v0 = 0, v1 = 0, v2 = 0, v3 = 0;
    if (base + 3 < L) {
        int4 x = *(const int4*)(d + base);
        v0 = x.x; v1 = x.y; v2 = x.z; v3 = x.w;
    } else {
        if (base < L) v0 = d[base];
        if (base + 1 < L) v1 = d[base + 1];
        if (base + 2 < L) v2 = d[base + 2];
    }
    v1 += v0; v2 += v1; v3 += v2;
    int inc = v3;
#pragma unroll
    for (int o = 1; o < 32; o <<= 1) {
        int n = __shfl_up_sync(0xffffffffu, inc, o);
        if (lane >= o) inc += n;
    }
    if (lane == 31) warpsum[wid] = inc;
    __syncthreads();
    if (wid == 0) {
        int s = (lane < 8) ? warpsum[lane] : 0;
#pragma unroll
        for (int o = 1; o < 8; o <<= 1) {
            int n = __shfl_up_sync(0xffffffffu, s, o);
            if (lane >= o) s += n;
        }
        if (lane < 8) warpsum[lane] = s;
    }
    __syncthreads();
    int off = inc - v3;
    if (wid > 0) off += warpsum[wid - 1];
    v0 += off; v1 += off; v2 += off; v3 += off;
    if (base + 3 < L) {
        *(int4*)(d + base) = make_int4(v0, v1, v2, v3);
    } else {
        if (base < L) d[base] = v0;
        if (base + 1 < L) d[base + 1] = v1;
        if (base + 2 < L) d[base + 2] = v2;
    }
    if (t == 255) bsums[blockIdx.x] = v3;
}

__global__ void k_scan_sums(int* __restrict__ bsums, int nb) {
    __shared__ int ws[4];
    const int t = threadIdx.x, lane = t & 31, wid = t >> 5;
    int v = (t < nb) ? bsums[t] : 0;
    int inc = v;
#pragma unroll
    for (int o = 1; o < 32; o <<= 1) {
        int n = __shfl_up_sync(0xffffffffu, inc, o);
        if (lane >= o) inc += n;
    }
    if (lane == 31) ws[wid] = inc;
    __syncthreads();
    if (t == 0) {
        int run = 0;
#pragma unroll
        for (int i = 0; i < 4; i++) { int tmp = ws[i]; ws[i] = run; run += tmp; }
    }
    __syncthreads();
    int excl = inc - v + ws[wid];
    if (t < nb) bsums[t] = excl;
}

__global__ void k_scatter(const int* __restrict__ rows, const int* __restrict__ cols,
                          const float* __restrict__ vals, int E) {
    int e = blockIdx.x * blockDim.x + threadIdx.x;
    if (e >= E) return;
    int r = rows[e];
    int idx = row_off(r) + atomicAdd(&g_cursor[r], 1);
    g_edges[idx] = make_int2(cols[e], __float_as_int(vals[e]));
}

// ---------------------------------------------------------------------------
// FP16 GEMM (m16n8k16, fp32 accum), BM=64 x BN=256 x BK=32, 256 threads,
// 2 CTAs/SM (so barrier stalls in one CTA are hidden by the other).
// A fp32 [M,512] read ONCE; B pre-converted fp16. Register double-buffered.
__global__ __launch_bounds__(256, 2) void f16_gemm1(
        const float* __restrict__ A, __half* __restrict__ C, int M, int N, int K) {
    constexpr int BM = 64;
    constexpr int BN = 256;
    constexpr int BK = 32;
    constexpr int WM = 32;       // 2 warps in M
    constexpr int WN = 64;       // 4 warps in N
    constexpr int MFR = 2;
    constexpr int NFR = 8;
    constexpr int AS2 = 20;
    constexpr int BS2 = BN + 8;

    __shared__ __align__(16) __half2 As[BM][AS2];
    __shared__ __align__(16) __half2 Bs[BK / 2][BS2];

    const int tid  = threadIdx.x;
    const int warp = tid >> 5;
    const int lane = tid & 31;
    const int wm = (warp & 1) * WM;
    const int wn = (warp >> 1) * WN;
    const int rowBase = blockIdx.y * BM;

    float acc[MFR][NFR][4];
#pragma unroll
    for (int i = 0; i < MFR; i++)
#pragma unroll
        for (int j = 0; j < NFR; j++)
#pragma unroll
            for (int q = 0; q < 4; q++) acc[i][j][q] = 0.f;

    // A: 64 rows x 32 cols fp32; 4 threads/row, 8 floats each
    const int arow = tid >> 2;
    const int acol0 = (tid & 3) * 8;
    // B: 16 k2-rows x 256 half2; 16 threads/row, 4 uint4 each
    const int brow2 = tid >> 4;          // 0..15
    const int bn4   = tid & 15;
    const int gr = rowBase + arow;
    const bool aok = (gr < M);
    const float* aBase = A + (size_t)gr * K + acol0;
    const uint32_t* bBase = g_W1h + (size_t)brow2 * N;

    // --- prologue: prefetch k0 = 0 ---
    float4 pa0 = make_float4(0.f, 0.f, 0.f, 0.f);
    float4 pa1 = make_float4(0.f, 0.f, 0.f, 0.f);
    uint4 pb[4];
    if (aok) { pa0 = *(const float4*)aBase; pa1 = *(const float4*)(aBase + 4); }
#pragma unroll
    for (int i = 0; i < 4; i++)
        pb[i] = *(const uint4*)(bBase + (bn4 + 16 * i) * 4);

    for (int k0 = 0; k0 < K; k0 += BK) {
        // --- store prefetched tile to smem (A: f32->f16 cvt; B: raw copy) ---
        {
            __half2 h[4];
            h[0] = __floats2half2_rn(pa0.x, pa0.y);
            h[1] = __floats2half2_rn(pa0.z, pa0.w);
            h[2] = __floats2half2_rn(pa1.x, pa1.y);
            h[3] = __floats2half2_rn(pa1.z, pa1.w);
            *(uint4*)&As[arow][acol0 / 2] = *(const uint4*)h;
        }
#pragma unroll
        for (int i = 0; i < 4; i++)
            *(uint4*)&Bs[brow2][(bn4 + 16 * i) * 4] = pb[i];
        __syncthreads();

        // --- prefetch next tile (overlaps the MMA phase below) ---
        const int kn = k0 + BK;
        if (kn < K) {
            if (aok) {
                pa0 = *(const float4*)(aBase + kn);
                pa1 = *(const float4*)(aBase + kn + 4);
            }
            const uint32_t* bp = bBase + (size_t)(kn / 2) * N;
#pragma unroll
            for (int i = 0; i < 4; i++)
                pb[i] = *(const uint4*)(bp + (bn4 + 16 * i) * 4);
        }

        // --- MMA phase ---
#pragma unroll
        for (int ks = 0; ks < BK / 16; ks++) {
            uint32_t afr[MFR][4];
            uint32_t bfr[NFR][2];
            const int ar = wm + (lane >> 2);
            const int kb = ks * 8 + (lane & 3);
#pragma unroll
            for (int mi = 0; mi < MFR; mi++) {
                afr[mi][0] = *(const uint32_t*)&As[ar + mi * 16 + 0][kb + 0];
                afr[mi][1] = *(const uint32_t*)&As[ar + mi * 16 + 8][kb + 0];
                afr[mi][2] = *(const uint32_t*)&As[ar + mi * 16 + 0][kb + 4];
                afr[mi][3] = *(const uint32_t*)&As[ar + mi * 16 + 8][kb + 4];
            }
            const int bc = wn + (lane >> 2);
#pragma unroll
            for (int ni = 0; ni < NFR; ni++) {
                bfr[ni][0] = *(const uint32_t*)&Bs[kb + 0][bc + ni * 8];
                bfr[ni][1] = *(const uint32_t*)&Bs[kb + 4][bc + ni * 8];
            }
#pragma unroll
            for (int mi = 0; mi < MFR; mi++)
#pragma unroll
                for (int ni = 0; ni < NFR; ni++)
                    mma_f16(acc[mi][ni], afr[mi], bfr[ni]);
        }
        __syncthreads();
    }

#pragma unroll
    for (int mi = 0; mi < MFR; mi++) {
#pragma unroll
        for (int ni = 0; ni < NFR; ni++) {
            const int r0 = rowBase + wm + mi * 16 + (lane >> 2);
            const int c0 = wn + ni * 8 + 2 * (lane & 3);
            if (r0 < M)
                *(__half2*)(C + (size_t)r0 * N + c0) =
                    __floats2half2_rn(acc[mi][ni][0], acc[mi][ni][1]);
            if (r0 + 8 < M)
                *(__half2*)(C + (size_t)(r0 + 8) * N + c0) =
                    __floats2half2_rn(acc[mi][ni][2], acc[mi][ni][3]);
        }
    }
}

// FP16 GEMM, fp16 A (direct copy), B pre-converted fp16; BM=128, BN=64,
// BK=32, 256 threads, warps 4x2. Register double-buffered. (GEMM2)
__global__ __launch_bounds__(256) void f16_gemm2(
        const __half* __restrict__ A, __half* __restrict__ C, int M, int N, int K) {
    constexpr int BM = 128;
    constexpr int BN = 64;
    constexpr int BK = 32;
    constexpr int WM = 32;
    constexpr int WN = 32;
    constexpr int MFR = 2;
    constexpr int NFR = 4;
    constexpr int AS2 = 20;
    constexpr int BS2 = BN + 8;

    __shared__ __align__(16) __half2 As[BM][AS2];
    __shared__ __align__(16) __half2 Bs[BK / 2][BS2];

    const int tid  = threadIdx.x;
    const int warp = tid >> 5;
    const int lane = tid & 31;
    const int wm = (warp % 4) * WM;
    const int wn = (warp / 4) * WN;
    const int rowBase = blockIdx.y * BM;

    float acc[MFR][NFR][4];
#pragma unroll
    for (int i = 0; i < MFR; i++)
#pragma unroll
        for (int j = 0; j < NFR; j++)
#pragma unroll
            for (int q = 0; q < 4; q++) acc[i][j][q] = 0.f;

    const int arow = tid >> 1;
    const int acolh = (tid & 1) * 16;
    const int brow2 = tid >> 4;
    const int bn4   = tid & 15;
    const int gr = rowBase + arow;
    const bool aok = (gr < M);
    const __half* aBase = A + (size_t)gr * K + acolh;
    const uint32_t* bBase = g_W2h + (size_t)brow2 * N;

    uint4 pq0 = make_uint4(0, 0, 0, 0), pq1 = make_uint4(0, 0, 0, 0);
    uint4 pb;
    if (aok) {
        pq0 = *(const uint4*)aBase;
        pq1 = *(const uint4*)(aBase + 8);
    }
    pb = *(const uint4*)(bBase + bn4 * 4);

    for (int k0 = 0; k0 < K; k0 += BK) {
        *(uint4*)&As[arow][acolh / 2 + 0] = pq0;
        *(uint4*)&As[arow][acolh / 2 + 4] = pq1;
        *(uint4*)&Bs[brow2][bn4 * 4] = pb;
        __syncthreads();

        const int kn = k0 + BK;
        if (kn < K) {
            if (aok) {
                pq0 = *(const uint4*)(aBase + kn);
                pq1 = *(const uint4*)(aBase + kn + 8);
            }
            pb = *(const uint4*)(bBase + (size_t)(kn / 2) * N + bn4 * 4);
        }

#pragma unroll
        for (int ks = 0; ks < BK / 16; ks++) {
            uint32_t afr[MFR][4];
            uint32_t bfr[NFR][2];
            const int ar = wm + (lane >> 2);
            const int kb = ks * 8 + (lane & 3);
#pragma unroll
            for (int mi = 0; mi < MFR; mi++) {
                afr[mi][0] = *(const uint32_t*)&As[ar + mi * 16 + 0][kb + 0];
                afr[mi][1] = *(const uint32_t*)&As[ar + mi * 16 + 8][kb + 0];
                afr[mi][2] = *(const uint32_t*)&As[ar + mi * 16 + 0][kb + 4];
                afr[mi][3] = *(const uint32_t*)&As[ar + mi * 16 + 8][kb + 4];
            }
            const int bc = wn + (lane >> 2);
#pragma unroll
            for (int ni = 0; ni < NFR; ni++) {
                bfr[ni][0] = *(const uint32_t*)&Bs[kb + 0][bc + ni * 8];
                bfr[ni][1] = *(const uint32_t*)&Bs[kb + 4][bc + ni * 8];
            }
#pragma unroll
            for (int mi = 0; mi < MFR; mi++)
#pragma unroll
                for (int ni = 0; ni < NFR; ni++)
                    mma_f16(acc[mi][ni], afr[mi], bfr[ni]);
        }
        __syncthreads();
    }

#pragma unroll
    for (int mi = 0; mi < MFR; mi++) {
#pragma unroll
        for (int ni = 0; ni < NFR; ni++) {
            const int r0 = rowBase + wm + mi * 16 + (lane >> 2);
            const int c0 = wn + ni * 8 + 2 * (lane & 3);
            if (r0 < M)
                *(__half2*)(C + (size_t)r0 * N + c0) =
                    __floats2half2_rn(acc[mi][ni][0], acc[mi][ni][1]);
            if (r0 + 8 < M)
                *(__half2*)(C + (size_t)(r0 + 8) * N + c0) =
                    __floats2half2_rn(acc[mi][ni][2], acc[mi][ni][3]);
        }
    }
}

// ---------------------------------------------------------------------------
// CSR SpMM, F=256, fp16 source (R12 form). One warp per row; lane owns 8 halfs.
__global__ void spmm_csr_f256h(const __half* __restrict__ X, const float* __restrict__ bias,
                               __half* __restrict__ Y) {
    const int r = (blockIdx.x * blockDim.x + threadIdx.x) >> 5;
    const int lane = threadIdx.x & 31;
    if (r >= NNODE) return;
    const int start = row_off(r);
    const int end   = row_off(r + 1);
    float acc[8];
#pragma unroll
    for (int i = 0; i < 8; i++) acc[i] = 0.f;
    const uint4* Xb = (const uint4*)X + lane;
    for (int base = start; base < end; base += 32) {
        const int m = min(32, end - base);
        int2 ev = make_int2(0, 0);
        if (lane < m) ev = g_edges[base + lane];
#pragma unroll 4
        for (int j = 0; j < m; j++) {
            const int   cj = __shfl_sync(0xffffffffu, ev.x, j);
            const float vj = __int_as_float(__shfl_sync(0xffffffffu, ev.y, j));
            uint4 q = __ldg(Xb + (size_t)cj * 32);
            const __half2* hp = (const __half2*)&q;
#pragma unroll
            for (int i = 0; i < 4; i++) {
                float2 f = __half22float2(hp[i]);
                acc[i * 2 + 0] = fmaf(vj, f.x, acc[i * 2 + 0]);
                acc[i * 2 + 1] = fmaf(vj, f.y, acc[i * 2 + 1]);
            }
        }
    }
    float4 b0 = __ldg((const float4*)bias + lane * 2);
    float4 b1 = __ldg((const float4*)bias + lane * 2 + 1);
    float bb[8] = {b0.x, b0.y, b0.z, b0.w, b1.x, b1.y, b1.z, b1.w};
    __half2 o[4];
#pragma unroll
    for (int i = 0; i < 4; i++)
        o[i] = __floats2half2_rn(fmaxf(acc[i * 2] + bb[i * 2], 0.f),
                                 fmaxf(acc[i * 2 + 1] + bb[i * 2 + 1], 0.f));
    uint4 ov = *(const uint4*)o;
    stcs_u4((uint4*)Y + (size_t)r * 32 + lane, ov);
}

// CSR SpMM F=64 (fp16 source) fused with bias + log_softmax (R12 form).
__global__ void spmm_csr_f64h_ls(const __half* __restrict__ X, const float* __restrict__ bias,
                                 float* __restrict__ out) {
    const int r = (blockIdx.x * blockDim.x + threadIdx.x) >> 5;
    const int lane = threadIdx.x & 31;
    if (r >= NNODE) return;
    const int start = row_off(r);
    const int end   = row_off(r + 1);
    float2 acc = make_float2(0.f, 0.f);
    const uint32_t* Xb = (const uint32_t*)X + lane;
    for (int base = start; base < end; base += 32) {
        const int m = min(32, end - base);
        int2 ev = make_int2(0, 0);
        if (lane < m) ev = g_edges[base + lane];
#pragma unroll 4
        for (int j = 0; j < m; j++) {
            const int   cj = __shfl_sync(0xffffffffu, ev.x, j);
            const float vj = __int_as_float(__shfl_sync(0xffffffffu, ev.y, j));
            uint32_t q = __ldg(Xb + (size_t)cj * 32);
            float2 xs = __half22float2(*(const __half2*)&q);
            acc.x = fmaf(vj, xs.x, acc.x);
            acc.y = fmaf(vj, xs.y, acc.y);
        }
    }
    float2 bb = __ldg((const float2*)bias + lane);
    float v0 = acc.x + bb.x;
    float v1 = acc.y + bb.y;
    float mx = fmaxf(v0, v1);
#pragma unroll
    for (int o = 16; o; o >>= 1) mx = fmaxf(mx, __shfl_xor_sync(0xffffffffu, mx, o));
    float s = __expf(v0 - mx) + __expf(v1 - mx);
#pragma unroll
    for (int o = 16; o; o >>= 1) s += __shfl_xor_sync(0xffffffffu, s, o);
    float lse = mx + __logf(s);
    *(float2*)(out + (size_t)r * 64 + lane * 2) = make_float2(v0 - lse, v1 - lse);
}

// ---------------------------------------------------------------------------
extern "C" void kernel_launch(void* const* d_in, const int* in_sizes, int n_in,
                              void* d_out, int out_size) {
    const float* x    = (const float*)d_in[0];
    const int*   erow = (const int*)d_in[1];
    const int*   ecol = (const int*)d_in[2];
    const float* eval_ = (const float*)d_in[3];
    const float* W1   = (const float*)d_in[4];
    const float* b1   = (const float*)d_in[5];
    const float* W2   = (const float*)d_in[6];
    const float* b2   = (const float*)d_in[7];
    float* out = (float*)d_out;

    const int E = in_sizes[1];
    const int M = in_sizes[0] / NF;  // 100000

    __half *xw1, *h, *hw2;
    int *rowptr, *bsums;
    cudaGetSymbolAddress((void**)&xw1, g_xw1);
    cudaGetSymbolAddress((void**)&h, g_h);
    cudaGetSymbolAddress((void**)&hw2, g_hw2);
    cudaGetSymbolAddress((void**)&rowptr, g_rowptr);
    cudaGetSymbolAddress((void**)&bsums, g_bsums);

    const int L = NNODE + 1;
    const int nscan = (L + 1023) / 1024;  // 98

    // One-time side resources (host-side only; no device memory involved).
    static cudaStream_t s2 = nullptr;
    static cudaEvent_t evFork = nullptr, evJoin = nullptr;
    if (!s2) {
        cudaStreamCreateWithFlags(&s2, cudaStreamNonBlocking);
        cudaEventCreateWithFlags(&evFork, cudaEventDisableTiming);
        cudaEventCreateWithFlags(&evJoin, cudaEventDisableTiming);
    }

    // Fork: CSR build on s2, concurrent with weight conversion + GEMM1.
    cudaEventRecord(evFork, 0);
    cudaStreamWaitEvent(s2, evFork, 0);

    // Host launch order keeps GEMM1 as the 4th launch for ncu.
    k_convW<<<((NF / 2) * NH + 255) / 256, 256>>>(W1, W2);            // 0 main
    k_zero_csr<<<(NNODE + 256) / 256, 256, 0, s2>>>();                // 1 s2
    k_hist4<<<(E / 4 + 255) / 256, 256, 0, s2>>>(erow, E);            // 2 s2
    f16_gemm1<<<dim3(1, (M + 63) / 64), 256>>>(x, xw1, M, NH, NF);    // 3 main
    k_scan_block<<<nscan, 256, 0, s2>>>(rowptr, L, bsums);            // 4 s2
    k_scan_sums<<<1, 128, 0, s2>>>(bsums, nscan);                     // 5 s2
    k_scatter<<<(E + 255) / 256, 256, 0, s2>>>(erow, ecol, eval_, E); // 6 s2
    cudaEventRecord(evJoin, s2);

    // Join: spmm1 needs both GEMM1 and the CSR structures.
    cudaStreamWaitEvent(0, evJoin, 0);

    // spmm1 (CSR gather, fp16 source L2-resident) + fused bias/relu
    {
        int blocks = (NNODE * 32 + 255) / 256;
        spmm_csr_f256h<<<blocks, 256>>>(xw1, b1, h);
    }

    // layer 2: HW2 = h @ W2  (fp16 tensor cores, pre-converted B)
    f16_gemm2<<<dim3(1, (M + 127) / 128), 256>>>(h, hw2, M, NC, NH);

    // spmm2 (CSR gather, fp16 source) + fused bias + log_softmax
    {
        int blocks = (NNODE * 32 + 255) / 256;
        spmm_csr_f64h_ls<<<blocks, 256>>>(hw2, b2, out);
    }
}